// round 8
// baseline (speedup 1.0000x reference)
#include <cuda_runtime.h>
#include <cuda_bf16.h>
#include <cstdint>
#include <cstddef>

#define HW   4096
#define CIN  256
#define CQK  32
#define CV   256
#define NB   8
#define MQKV 320
#define SSEG 64            // column-sum segments (HW/64)

typedef __nv_bfloat16 bf16;

// ---------------- scratch -----------------------------------------------
__device__ bf16  g_wh[MQKV * CIN];
__device__ bf16  g_wl[MQKV * CIN];
__device__ bf16  g_woh[CIN * CV];
__device__ bf16  g_wol[CIN * CV];
__device__ bf16  g_xth[(size_t)NB * HW * CIN];        // x^T [l, c]
__device__ bf16  g_xtl[(size_t)NB * HW * CIN];
__device__ float g_qkv[(size_t)NB * MQKV * HW];       // fp32 q,k,v [m, l]
__device__ bf16  g_qkTh[(size_t)NB * HW * 64];        // [l][0:32]=qT, [32:64]=kT
__device__ bf16  g_qkTl[(size_t)NB * HW * 64];
__device__ float g_sp[(size_t)NB * SSEG * HW];        // partial col sums
__device__ float g_s[(size_t)NB * HW];
__device__ bf16  g_phi[(size_t)NB * HW * HW];         // P=exp(E) hi [j,i]
__device__ bf16  g_plo[(size_t)NB * HW * HW];         // P lo
__device__ bf16  g_vhi[(size_t)NB * CV * HW];         // (V/s) hi [v,i]
__device__ bf16  g_vlo[(size_t)NB * CV * HW];
__device__ bf16  g_oth[(size_t)NB * HW * CV];         // O^T hi [l, v]
__device__ bf16  g_otl[(size_t)NB * HW * CV];

// ---------------- helpers -------------------------------------------------
static __device__ __forceinline__ uint32_t smem_u32(const void* p) {
    uint32_t a;
    asm("{ .reg .u64 t; cvta.to.shared.u64 t, %1; cvt.u32.u64 %0, t; }" : "=r"(a) : "l"(p));
    return a;
}
#define SW64(x) ((x) ^ (((x) >> 3) & 0x30))
#define LDSM4(r0, r1, r2, r3, addr) \
    asm volatile("ldmatrix.sync.aligned.m8n8.x4.shared.b16 {%0,%1,%2,%3}, [%4];" \
                 : "=r"(r0), "=r"(r1), "=r"(r2), "=r"(r3) : "r"(addr))
#define LDSM2(r0, r1, addr) \
    asm volatile("ldmatrix.sync.aligned.m8n8.x2.shared.b16 {%0,%1}, [%2];" \
                 : "=r"(r0), "=r"(r1) : "r"(addr))
#define MMA16816(c, a, b) \
    asm volatile("mma.sync.aligned.m16n8k16.row.col.f32.bf16.bf16.f32 " \
                 "{%0,%1,%2,%3}, {%4,%5,%6,%7}, {%8,%9}, {%0,%1,%2,%3};" \
                 : "+f"((c)[0]), "+f"((c)[1]), "+f"((c)[2]), "+f"((c)[3]) \
                 : "r"((a)[0]), "r"((a)[1]), "r"((a)[2]), "r"((a)[3]), \
                   "r"((b)[0]), "r"((b)[1]))

// ---------------- weight split --------------------------------------------
__global__ void split_w(const float* __restrict__ Wq, const float* __restrict__ Wk,
                        const float* __restrict__ Wv, const float* __restrict__ Wo) {
    int i = blockIdx.x * 256 + threadIdx.x;
    if (i < MQKV * CIN) {
        float v = (i < CQK * CIN) ? Wq[i]
                : (i < 2 * CQK * CIN) ? Wk[i - CQK * CIN]
                : Wv[i - 2 * CQK * CIN];
        bf16 h = __float2bfloat16(v);
        g_wh[i] = h;
        g_wl[i] = __float2bfloat16(v - __bfloat162float(h));
    } else {
        int j = i - MQKV * CIN;
        if (j < CIN * CV) {
            float v = Wo[j];
            bf16 h = __float2bfloat16(v);
            g_woh[j] = h;
            g_wol[j] = __float2bfloat16(v - __bfloat162float(h));
        }
    }
}

// ---------------- transpose + bf16 split: src[R,HW] -> dst[HW,R] -----------
__global__ __launch_bounds__(256)
void trsp(const float* __restrict__ src, bf16* __restrict__ dhi, bf16* __restrict__ dlo,
          int R, size_t sStride, size_t dStride) {
    __shared__ float t[32][33];
    int n = blockIdx.z;
    src += (size_t)n * sStride;
    dhi += (size_t)n * dStride;
    dlo += (size_t)n * dStride;
    int c0 = blockIdx.x * 32, r0 = blockIdx.y * 32;
    int tx = threadIdx.x, ty = threadIdx.y;
    #pragma unroll
    for (int it = 0; it < 4; it++)
        t[ty + 8 * it][tx] = src[(size_t)(r0 + ty + 8 * it) * HW + c0 + tx];
    __syncthreads();
    #pragma unroll
    for (int it = 0; it < 4; it++) {
        float v = t[tx][ty + 8 * it];
        bf16 h = __float2bfloat16(v);
        size_t o = (size_t)(c0 + ty + 8 * it) * R + r0 + tx;
        dhi[o] = h;
        dlo[o] = __float2bfloat16(v - __bfloat162float(h));
    }
}

// ---------------- QKV projection HMMA ---------------------------------------
__global__ __launch_bounds__(256, 2)
void qkv_hmma() {
    __shared__ __align__(16) bf16 sAh[64 * 32], sAl[64 * 32];
    __shared__ __align__(16) bf16 sBh[128 * 32], sBl[128 * 32];
    int tid = threadIdx.x, lane = tid & 31, wid = tid >> 5;
    int wm = wid & 1, wn = wid >> 1;
    int n = blockIdx.z, m0 = blockIdx.y * 64, l0 = blockIdx.x * 128;

    const bf16* xth = g_xth + (size_t)n * HW * CIN;
    const bf16* xtl = g_xtl + (size_t)n * HW * CIN;
    uint32_t sa_h = smem_u32(sAh), sa_l = smem_u32(sAl);
    uint32_t sb_h = smem_u32(sBh), sb_l = smem_u32(sBl);

    float acc[2][4][4] = {};

    for (int ck = 0; ck < CIN / 32; ck++) {
        {
            int row = tid >> 2, ch = tid & 3;
            uint32_t sw = SW64(row * 64 + ch * 16);
            size_t ga = (size_t)(m0 + row) * CIN + ck * 32 + ch * 8;
            *(float4*)((char*)sAh + sw) = *(const float4*)(const void*)(g_wh + ga);
            *(float4*)((char*)sAl + sw) = *(const float4*)(const void*)(g_wl + ga);
        }
        #pragma unroll
        for (int t = 0; t < 2; t++) {
            int idx = tid + t * 256;
            int row = idx >> 2, ch = idx & 3;
            uint32_t sw = SW64(row * 64 + ch * 16);
            size_t gb = (size_t)(l0 + row) * CIN + ck * 32 + ch * 8;
            *(float4*)((char*)sBh + sw) = *(const float4*)(const void*)(xth + gb);
            *(float4*)((char*)sBl + sw) = *(const float4*)(const void*)(xtl + gb);
        }
        __syncthreads();

        #pragma unroll
        for (int ks = 0; ks < 2; ks++) {
            uint32_t a[2][4], bh[4][2], bl[4][2];
            uint32_t a_off[2];
            #pragma unroll
            for (int mt = 0; mt < 2; mt++) {
                int r = wm * 32 + mt * 16 + (lane & 15);
                a_off[mt] = SW64(r * 64 + ks * 32 + (lane >> 4) * 16);
                LDSM4(a[mt][0], a[mt][1], a[mt][2], a[mt][3], sa_h + a_off[mt]);
            }
            #pragma unroll
            for (int nt = 0; nt < 4; nt++) {
                int r = wn * 32 + nt * 8 + (lane & 7);
                uint32_t sw = SW64(r * 64 + ks * 32 + ((lane >> 3) & 1) * 16);
                LDSM2(bh[nt][0], bh[nt][1], sb_h + sw);
                LDSM2(bl[nt][0], bl[nt][1], sb_l + sw);
            }
            #pragma unroll
            for (int mt = 0; mt < 2; mt++)
                #pragma unroll
                for (int nt = 0; nt < 4; nt++) {
                    MMA16816(acc[mt][nt], a[mt], bh[nt]);
                    MMA16816(acc[mt][nt], a[mt], bl[nt]);
                }
            #pragma unroll
            for (int mt = 0; mt < 2; mt++)
                LDSM4(a[mt][0], a[mt][1], a[mt][2], a[mt][3], sa_l + a_off[mt]);
            #pragma unroll
            for (int mt = 0; mt < 2; mt++)
                #pragma unroll
                for (int nt = 0; nt < 4; nt++)
                    MMA16816(acc[mt][nt], a[mt], bh[nt]);
        }
        __syncthreads();
    }

    #pragma unroll
    for (int mt = 0; mt < 2; mt++) {
        int m = m0 + wm * 32 + mt * 16 + (lane >> 2);
        float* r0p = g_qkv + ((size_t)n * MQKV + m) * HW + l0 + wn * 32 + (lane & 3) * 2;
        float* r1p = r0p + 8 * HW;
        #pragma unroll
        for (int nt = 0; nt < 4; nt++) {
            *(float2*)(r0p + nt * 8) = make_float2(acc[mt][nt][0], acc[mt][nt][1]);
            *(float2*)(r1p + nt * 8) = make_float2(acc[mt][nt][2], acc[mt][nt][3]);
        }
    }
}

// ---------------- Et + exp fused: P[j,i] = exp(kT_j . qT_i), partial sums ---
// grid (HW/128 i, HW/128 j, NB); 8 warps (2x4), warp 64x32.
__global__ __launch_bounds__(256, 2)
void et_exp_hmma() {
    __shared__ __align__(16) bf16 sAh[128 * 32], sAl[128 * 32];
    __shared__ __align__(16) bf16 sBh[128 * 32], sBl[128 * 32];
    int tid = threadIdx.x, lane = tid & 31, wid = tid >> 5;
    int wm = wid & 1, wn = wid >> 1;
    int n = blockIdx.z, i0 = blockIdx.x * 128, j0 = blockIdx.y * 128;

    const bf16* th = g_qkTh + (size_t)n * HW * 64;
    const bf16* tl = g_qkTl + (size_t)n * HW * 64;
    uint32_t sa_h = smem_u32(sAh), sa_l = smem_u32(sAl);
    uint32_t sb_h = smem_u32(sBh), sb_l = smem_u32(sBl);

    #pragma unroll
    for (int t = 0; t < 2; t++) {
        int idx = tid + t * 256;
        int row = idx >> 2, ch = idx & 3;
        uint32_t sw = SW64(row * 64 + ch * 16);
        *(float4*)((char*)sAh + sw) = *(const float4*)(const void*)(th + (size_t)(j0 + row) * 64 + 32 + ch * 8);
        *(float4*)((char*)sAl + sw) = *(const float4*)(const void*)(tl + (size_t)(j0 + row) * 64 + 32 + ch * 8);
        *(float4*)((char*)sBh + sw) = *(const float4*)(const void*)(th + (size_t)(i0 + row) * 64 + ch * 8);
        *(float4*)((char*)sBl + sw) = *(const float4*)(const void*)(tl + (size_t)(i0 + row) * 64 + ch * 8);
    }
    __syncthreads();

    float acc[4][4][4] = {};
    #pragma unroll
    for (int ks = 0; ks < 2; ks++) {
        uint32_t a[4][4], bh[4][2], bl[4][2];
        uint32_t a_off[4];
        #pragma unroll
        for (int mt = 0; mt < 4; mt++) {
            int r = wm * 64 + mt * 16 + (lane & 15);
            a_off[mt] = SW64(r * 64 + ks * 32 + (lane >> 4) * 16);
            LDSM4(a[mt][0], a[mt][1], a[mt][2], a[mt][3], sa_h + a_off[mt]);
        }
        #pragma unroll
        for (int nt = 0; nt < 4; nt++) {
            int r = wn * 32 + nt * 8 + (lane & 7);
            uint32_t sw = SW64(r * 64 + ks * 32 + ((lane >> 3) & 1) * 16);
            LDSM2(bh[nt][0], bh[nt][1], sb_h + sw);
            LDSM2(bl[nt][0], bl[nt][1], sb_l + sw);
        }
        #pragma unroll
        for (int mt = 0; mt < 4; mt++)
            #pragma unroll
            for (int nt = 0; nt < 4; nt++) {
                MMA16816(acc[mt][nt], a[mt], bh[nt]);
                MMA16816(acc[mt][nt], a[mt], bl[nt]);
            }
        #pragma unroll
        for (int mt = 0; mt < 4; mt++)
            LDSM4(a[mt][0], a[mt][1], a[mt][2], a[mt][3], sa_l + a_off[mt]);
        #pragma unroll
        for (int mt = 0; mt < 4; mt++)
            #pragma unroll
            for (int nt = 0; nt < 4; nt++)
                MMA16816(acc[mt][nt], a[mt], bh[nt]);
    }

    // epilogue: p = exp(e) (no max shift: |e| <~ 4, fp32-safe; softmax invariant)
    bf16* phi = g_phi + (size_t)n * HW * HW;
    bf16* plo = g_plo + (size_t)n * HW * HW;
    float cs[4][2];
    #pragma unroll
    for (int nt = 0; nt < 4; nt++) { cs[nt][0] = 0.0f; cs[nt][1] = 0.0f; }

    #pragma unroll
    for (int mt = 0; mt < 4; mt++) {
        int j = j0 + wm * 64 + mt * 16 + (lane >> 2);
        #pragma unroll
        for (int nt = 0; nt < 4; nt++) {
            int ib = i0 + wn * 32 + nt * 8 + (lane & 3) * 2;
            float p0 = __expf(acc[mt][nt][0]);
            float p1 = __expf(acc[mt][nt][1]);
            float p2 = __expf(acc[mt][nt][2]);
            float p3 = __expf(acc[mt][nt][3]);
            bf16 h0 = __float2bfloat16(p0), h1 = __float2bfloat16(p1);
            bf16 h2 = __float2bfloat16(p2), h3 = __float2bfloat16(p3);
            __nv_bfloat162 hv0; hv0.x = h0; hv0.y = h1;
            __nv_bfloat162 hv1; hv1.x = h2; hv1.y = h3;
            __nv_bfloat162 lv0; lv0.x = __float2bfloat16(p0 - __bfloat162float(h0));
                                lv0.y = __float2bfloat16(p1 - __bfloat162float(h1));
            __nv_bfloat162 lv1; lv1.x = __float2bfloat16(p2 - __bfloat162float(h2));
                                lv1.y = __float2bfloat16(p3 - __bfloat162float(h3));
            *(__nv_bfloat162*)(phi + (size_t)j * HW + ib) = hv0;
            *(__nv_bfloat162*)(phi + (size_t)(j + 8) * HW + ib) = hv1;
            *(__nv_bfloat162*)(plo + (size_t)j * HW + ib) = lv0;
            *(__nv_bfloat162*)(plo + (size_t)(j + 8) * HW + ib) = lv1;
            cs[nt][0] += p0 + p2;
            cs[nt][1] += p1 + p3;
        }
    }
    // reduce column sums across lane>>2 (8 j-slots), write per-(seg,i)
    int seg = blockIdx.y * 2 + wm;
    #pragma unroll
    for (int nt = 0; nt < 4; nt++) {
        #pragma unroll
        for (int c = 0; c < 2; c++) {
            float s = cs[nt][c];
            s += __shfl_xor_sync(0xFFFFFFFFu, s, 4);
            s += __shfl_xor_sync(0xFFFFFFFFu, s, 8);
            s += __shfl_xor_sync(0xFFFFFFFFu, s, 16);
            if ((lane >> 2) == 0) {
                int i = i0 + wn * 32 + nt * 8 + (lane & 3) * 2 + c;
                g_sp[((size_t)n * SSEG + seg) * HW + i] = s;
            }
        }
    }
}

// ---------------- finalize col sums, V' = V / s ------------------------------
__global__ __launch_bounds__(256)
void sum_fin() {
    size_t t = (size_t)blockIdx.x * 256 + threadIdx.x;
    size_t n = t / HW, i = t % HW;
    float s = 0.0f;
    #pragma unroll
    for (int sg = 0; sg < SSEG; sg++)
        s += g_sp[(n * SSEG + sg) * HW + i];
    g_s[t] = s;
}
__global__ __launch_bounds__(256)
void conv_v() {
    size_t idx = (size_t)blockIdx.x * 256 + threadIdx.x;
    size_t n = idx / ((size_t)CV * HW);
    size_t rem = idx % ((size_t)CV * HW);
    size_t r = rem / HW, i = rem % HW;
    float v = g_qkv[((size_t)n * MQKV + 2 * CQK + r) * HW + i];
    float vv = v / g_s[n * HW + i];
    bf16 h = __float2bfloat16(vv);
    g_vhi[idx] = h;
    g_vlo[idx] = __float2bfloat16(vv - __bfloat162float(h));
}

// ---------------- O^T = P @ V'^T  (3 products, writes bf16 split) -----------
// grid (CV/128 v, HW/128 j, NB); m-dim = j, n-dim = v.
#define BK 32
__global__ __launch_bounds__(256, 2)
void mma_ot() {
    __shared__ __align__(16) bf16 sAh[128 * BK], sAl[128 * BK];
    __shared__ __align__(16) bf16 sBh[128 * BK], sBl[128 * BK];
    int tid = threadIdx.x, lane = tid & 31, wid = tid >> 5;
    int wm = wid & 1, wn = wid >> 1;
    int n = blockIdx.z, v0 = blockIdx.x * 128, j0 = blockIdx.y * 128;

    const bf16* Ph = g_phi + (size_t)n * HW * HW + (size_t)j0 * HW;
    const bf16* Pl = g_plo + (size_t)n * HW * HW + (size_t)j0 * HW;
    const bf16* Vh = g_vhi + ((size_t)n * CV + v0) * HW;
    const bf16* Vl = g_vlo + ((size_t)n * CV + v0) * HW;
    uint32_t sa_h = smem_u32(sAh), sa_l = smem_u32(sAl);
    uint32_t sb_h = smem_u32(sBh), sb_l = smem_u32(sBl);

    float acc[4][4][4] = {};

    for (int ck = 0; ck < HW / BK; ck++) {
        #pragma unroll
        for (int t = 0; t < 2; t++) {
            int idx = tid + t * 256;
            int row = idx >> 2, ch = idx & 3;
            uint32_t sw = SW64(row * 64 + ch * 16);
            size_t go = (size_t)row * HW + (size_t)ck * BK + ch * 8;
            *(float4*)((char*)sAh + sw) = *(const float4*)(const void*)(Ph + go);
            *(float4*)((char*)sAl + sw) = *(const float4*)(const void*)(Pl + go);
            *(float4*)((char*)sBh + sw) = *(const float4*)(const void*)(Vh + go);
            *(float4*)((char*)sBl + sw) = *(const float4*)(const void*)(Vl + go);
        }
        __syncthreads();

        #pragma unroll
        for (int ks = 0; ks < 2; ks++) {
            uint32_t a[4][4], bh[4][2], bl[4][2];
            uint32_t a_off[4];
            #pragma unroll
            for (int mt = 0; mt < 4; mt++) {
                int r = wm * 64 + mt * 16 + (lane & 15);
                a_off[mt] = SW64(r * 64 + ks * 32 + (lane >> 4) * 16);
                LDSM4(a[mt][0], a[mt][1], a[mt][2], a[mt][3], sa_h + a_off[mt]);
            }
            #pragma unroll
            for (int nt = 0; nt < 4; nt++) {
                int r = wn * 32 + nt * 8 + (lane & 7);
                uint32_t sw = SW64(r * 64 + ks * 32 + ((lane >> 3) & 1) * 16);
                LDSM2(bh[nt][0], bh[nt][1], sb_h + sw);
                LDSM2(bl[nt][0], bl[nt][1], sb_l + sw);
            }
            // Phi*Vhi + Phi*Vlo
            #pragma unroll
            for (int mt = 0; mt < 4; mt++)
                #pragma unroll
                for (int nt = 0; nt < 4; nt++) {
                    MMA16816(acc[mt][nt], a[mt], bh[nt]);
                    MMA16816(acc[mt][nt], a[mt], bl[nt]);
                }
            // Plo*Vhi
            #pragma unroll
            for (int mt = 0; mt < 4; mt++)
                LDSM4(a[mt][0], a[mt][1], a[mt][2], a[mt][3], sa_l + a_off[mt]);
            #pragma unroll
            for (int mt = 0; mt < 4; mt++)
                #pragma unroll
                for (int nt = 0; nt < 4; nt++)
                    MMA16816(acc[mt][nt], a[mt], bh[nt]);
        }
        __syncthreads();
    }

    // epilogue: write O^T[j, v] as bf16 hi/lo (input layout for wo_hmma)
    bf16* oth = g_oth + (size_t)n * HW * CV;
    bf16* otl = g_otl + (size_t)n * HW * CV;
    #pragma unroll
    for (int mt = 0; mt < 4; mt++) {
        int j = j0 + wm * 64 + mt * 16 + (lane >> 2);
        int vb = v0 + wn * 32 + (lane & 3) * 2;
        #pragma unroll
        for (int nt = 0; nt < 4; nt++) {
            float p0 = acc[mt][nt][0], p1 = acc[mt][nt][1];
            float p2 = acc[mt][nt][2], p3 = acc[mt][nt][3];
            bf16 h0 = __float2bfloat16(p0), h1 = __float2bfloat16(p1);
            bf16 h2 = __float2bfloat16(p2), h3 = __float2bfloat16(p3);
            __nv_bfloat162 hv0; hv0.x = h0; hv0.y = h1;
            __nv_bfloat162 hv1; hv1.x = h2; hv1.y = h3;
            __nv_bfloat162 lv0; lv0.x = __float2bfloat16(p0 - __bfloat162float(h0));
                                lv0.y = __float2bfloat16(p1 - __bfloat162float(h1));
            __nv_bfloat162 lv1; lv1.x = __float2bfloat16(p2 - __bfloat162float(h2));
                                lv1.y = __float2bfloat16(p3 - __bfloat162float(h3));
            *(__nv_bfloat162*)(oth + (size_t)j * CV + vb + nt * 8) = hv0;
            *(__nv_bfloat162*)(oth + (size_t)(j + 8) * CV + vb + nt * 8) = hv1;
            *(__nv_bfloat162*)(otl + (size_t)j * CV + vb + nt * 8) = lv0;
            *(__nv_bfloat162*)(otl + (size_t)(j + 8) * CV + vb + nt * 8) = lv1;
        }
    }
}

// ---------------- out = gamma * Wo @ O ---------------------------------------
__global__ __launch_bounds__(256, 2)
void wo_hmma(float* __restrict__ out, const float* __restrict__ gammaPtr) {
    __shared__ __align__(16) bf16 sAh[128 * 32], sAl[128 * 32];
    __shared__ __align__(16) bf16 sBh[128 * 32], sBl[128 * 32];
    int tid = threadIdx.x, lane = tid & 31, wid = tid >> 5;
    int wm = wid & 1, wn = wid >> 1;
    int n = blockIdx.z, o0 = blockIdx.y * 128, l0 = blockIdx.x * 128;

    const bf16* oth = g_oth + (size_t)n * HW * CV;
    const bf16* otl = g_otl + (size_t)n * HW * CV;
    uint32_t sa_h = smem_u32(sAh), sa_l = smem_u32(sAl);
    uint32_t sb_h = smem_u32(sBh), sb_l = smem_u32(sBl);

    float acc[4][4][4] = {};

    for (int ck = 0; ck < CV / 32; ck++) {
        #pragma unroll
        for (int t = 0; t < 2; t++) {
            int idx = tid + t * 256;
            int row = idx >> 2, ch = idx & 3;
            uint32_t sw = SW64(row * 64 + ch * 16);
            size_t ga = (size_t)(o0 + row) * CV + ck * 32 + ch * 8;
            size_t gb = (size_t)(l0 + row) * CV + ck * 32 + ch * 8;
            *(float4*)((char*)sAh + sw) = *(const float4*)(const void*)(g_woh + ga);
            *(float4*)((char*)sAl + sw) = *(const float4*)(const void*)(g_wol + ga);
            *(float4*)((char*)sBh + sw) = *(const float4*)(const void*)(oth + gb);
            *(float4*)((char*)sBl + sw) = *(const float4*)(const void*)(otl + gb);
        }
        __syncthreads();

        #pragma unroll
        for (int ks = 0; ks < 2; ks++) {
            uint32_t a[4][4], bh[4][2], bl[4][2];
            uint32_t a_off[4];
            #pragma unroll
            for (int mt = 0; mt < 4; mt++) {
                int r = wm * 64 + mt * 16 + (lane & 15);
                a_off[mt] = SW64(r * 64 + ks * 32 + (lane >> 4) * 16);
                LDSM4(a[mt][0], a[mt][1], a[mt][2], a[mt][3], sa_h + a_off[mt]);
            }
            #pragma unroll
            for (int nt = 0; nt < 4; nt++) {
                int r = wn * 32 + nt * 8 + (lane & 7);
                uint32_t sw = SW64(r * 64 + ks * 32 + ((lane >> 3) & 1) * 16);
                LDSM2(bh[nt][0], bh[nt][1], sb_h + sw);
                LDSM2(bl[nt][0], bl[nt][1], sb_l + sw);
            }
            #pragma unroll
            for (int mt = 0; mt < 4; mt++)
                #pragma unroll
                for (int nt = 0; nt < 4; nt++) {
                    MMA16816(acc[mt][nt], a[mt], bh[nt]);
                    MMA16816(acc[mt][nt], a[mt], bl[nt]);
                }
            #pragma unroll
            for (int mt = 0; mt < 4; mt++)
                LDSM4(a[mt][0], a[mt][1], a[mt][2], a[mt][3], sa_l + a_off[mt]);
            #pragma unroll
            for (int mt = 0; mt < 4; mt++)
                #pragma unroll
                for (int nt = 0; nt < 4; nt++)
                    MMA16816(acc[mt][nt], a[mt], bh[nt]);
        }
        __syncthreads();
    }

    float gamma = *gammaPtr;
    #pragma unroll
    for (int mt = 0; mt < 4; mt++) {
        int o = o0 + wm * 64 + mt * 16 + (lane >> 2);
        float* r0p = out + ((size_t)n * CIN + o) * HW + l0 + wn * 32 + (lane & 3) * 2;
        float* r1p = r0p + 8 * HW;
        #pragma unroll
        for (int nt = 0; nt < 4; nt++) {
            *(float2*)(r0p + nt * 8) = make_float2(gamma * acc[mt][nt][0], gamma * acc[mt][nt][1]);
            *(float2*)(r1p + nt * 8) = make_float2(gamma * acc[mt][nt][2], gamma * acc[mt][nt][3]);
        }
    }
}

// ---------------- launch ----------------------------------------------------
extern "C" void kernel_launch(void* const* d_in, const int* in_sizes, int n_in,
                              void* d_out, int out_size) {
    const float* x     = (const float*)d_in[0];
    const float* Wq    = (const float*)d_in[1];
    const float* Wk    = (const float*)d_in[2];
    const float* Wv    = (const float*)d_in[3];
    const float* Wo    = (const float*)d_in[4];
    const float* gamma = (const float*)d_in[5];
    float* out = (float*)d_out;

    float* qkv = nullptr; cudaGetSymbolAddress((void**)&qkv, g_qkv);
    bf16* xth = nullptr;  cudaGetSymbolAddress((void**)&xth, g_xth);
    bf16* xtl = nullptr;  cudaGetSymbolAddress((void**)&xtl, g_xtl);
    bf16* qkh = nullptr;  cudaGetSymbolAddress((void**)&qkh, g_qkTh);
    bf16* qkl = nullptr;  cudaGetSymbolAddress((void**)&qkl, g_qkTl);

    // 1. split weights
    split_w<<<(MQKV * CIN + CIN * CV + 255) / 256, 256>>>(Wq, Wk, Wv, Wo);
    // 2. xT split [HW, 256]
    trsp<<<dim3(HW / 32, CIN / 32, NB), dim3(32, 8)>>>(
        x, xth, xtl, CIN, (size_t)CIN * HW, (size_t)HW * CIN);
    // 3. QKV projection (HMMA)
    qkv_hmma<<<dim3(HW / 128, MQKV / 64, NB), 256>>>();
    // 4. qT/kT split [HW, 64]
    trsp<<<dim3(HW / 32, 2, NB), dim3(32, 8)>>>(
        qkv, qkh, qkl, 64, (size_t)MQKV * HW, (size_t)HW * 64);
    // 5. Et + exp fused -> P hi/lo, partial col sums
    et_exp_hmma<<<dim3(HW / 128, HW / 128, NB), 256>>>();
    // 6. finalize sums; V' = V / s
    sum_fin<<<(NB * HW) / 256, 256>>>();
    conv_v<<<(NB * CV * HW) / 256, 256>>>();
    // 7. O^T = P @ V'^T  (HMMA, writes bf16 split directly)
    mma_ot<<<dim3(CV / 128, HW / 128, NB), 256>>>();
    // 8. out = gamma * Wo @ O  (HMMA)
    wo_hmma<<<dim3(HW / 128, CIN / 128, NB), 256>>>(out, gamma);
}

// round 9
// speedup vs baseline: 2.0687x; 2.0687x over previous
#include <cuda_runtime.h>
#include <cuda_bf16.h>
#include <cuda_fp16.h>
#include <cstdint>
#include <cstddef>

#define HW   4096
#define CIN  256
#define CQK  32
#define CV   256
#define NB   8
#define MQKV 320
#define SSEG 64
#define VSCALE 1024.0f

typedef __nv_bfloat16 bf16;

// ---------------- scratch -----------------------------------------------
__device__ bf16  g_wh[MQKV * CIN];
__device__ bf16  g_wl[MQKV * CIN];
__device__ bf16  g_woh[CIN * CV];
__device__ bf16  g_wol[CIN * CV];
__device__ bf16  g_xth[(size_t)NB * HW * CIN];
__device__ bf16  g_xtl[(size_t)NB * HW * CIN];
__device__ float g_qkv[(size_t)NB * MQKV * HW];
__device__ bf16  g_qkTh[(size_t)NB * HW * 64];
__device__ bf16  g_qkTl[(size_t)NB * HW * 64];
__device__ float g_sp[(size_t)NB * SSEG * HW];
__device__ float g_s[(size_t)NB * HW];
__device__ __half g_pf[(size_t)NB * HW * HW];         // P=exp(E) fp16 [j,i]
__device__ __half g_vf[(size_t)NB * CV * HW];         // (V/s)*1024 fp16 [v,i]
__device__ bf16  g_oth[(size_t)NB * HW * CV];         // O^T hi [l, v]
__device__ bf16  g_otl[(size_t)NB * HW * CV];

// ---------------- helpers -------------------------------------------------
static __device__ __forceinline__ uint32_t smem_u32(const void* p) {
    uint32_t a;
    asm("{ .reg .u64 t; cvta.to.shared.u64 t, %1; cvt.u32.u64 %0, t; }" : "=r"(a) : "l"(p));
    return a;
}
#define SW64(x)  ((x) ^ (((x) >> 3) & 0x30))
#define SW128(x) ((x) ^ (((x) >> 3) & 0x70))
#define LDSM4(r0, r1, r2, r3, addr) \
    asm volatile("ldmatrix.sync.aligned.m8n8.x4.shared.b16 {%0,%1,%2,%3}, [%4];" \
                 : "=r"(r0), "=r"(r1), "=r"(r2), "=r"(r3) : "r"(addr))
#define LDSM2(r0, r1, addr) \
    asm volatile("ldmatrix.sync.aligned.m8n8.x2.shared.b16 {%0,%1}, [%2];" \
                 : "=r"(r0), "=r"(r1) : "r"(addr))
#define MMA16816(c, a, b) \
    asm volatile("mma.sync.aligned.m16n8k16.row.col.f32.bf16.bf16.f32 " \
                 "{%0,%1,%2,%3}, {%4,%5,%6,%7}, {%8,%9}, {%0,%1,%2,%3};" \
                 : "+f"((c)[0]), "+f"((c)[1]), "+f"((c)[2]), "+f"((c)[3]) \
                 : "r"((a)[0]), "r"((a)[1]), "r"((a)[2]), "r"((a)[3]), \
                   "r"((b)[0]), "r"((b)[1]))
#define MMA16816H(c, a, b) \
    asm volatile("mma.sync.aligned.m16n8k16.row.col.f32.f16.f16.f32 " \
                 "{%0,%1,%2,%3}, {%4,%5,%6,%7}, {%8,%9}, {%0,%1,%2,%3};" \
                 : "+f"((c)[0]), "+f"((c)[1]), "+f"((c)[2]), "+f"((c)[3]) \
                 : "r"((a)[0]), "r"((a)[1]), "r"((a)[2]), "r"((a)[3]), \
                   "r"((b)[0]), "r"((b)[1]))
#define CPA16(saddr, gptr) \
    asm volatile("cp.async.cg.shared.global [%0], [%1], 16;" :: "r"(saddr), "l"(gptr))
#define CPA_COMMIT() asm volatile("cp.async.commit_group;")
#define CPA_WAIT(N)  asm volatile("cp.async.wait_group %0;" :: "n"(N))

// ---------------- weight split --------------------------------------------
__global__ void split_w(const float* __restrict__ Wq, const float* __restrict__ Wk,
                        const float* __restrict__ Wv, const float* __restrict__ Wo) {
    int i = blockIdx.x * 256 + threadIdx.x;
    if (i < MQKV * CIN) {
        float v = (i < CQK * CIN) ? Wq[i]
                : (i < 2 * CQK * CIN) ? Wk[i - CQK * CIN]
                : Wv[i - 2 * CQK * CIN];
        bf16 h = __float2bfloat16(v);
        g_wh[i] = h;
        g_wl[i] = __float2bfloat16(v - __bfloat162float(h));
    } else {
        int j = i - MQKV * CIN;
        if (j < CIN * CV) {
            float v = Wo[j];
            bf16 h = __float2bfloat16(v);
            g_woh[j] = h;
            g_wol[j] = __float2bfloat16(v - __bfloat162float(h));
        }
    }
}

// ---------------- transpose + bf16 split ------------------------------------
__global__ __launch_bounds__(256)
void trsp(const float* __restrict__ src, bf16* __restrict__ dhi, bf16* __restrict__ dlo,
          int R, size_t sStride, size_t dStride) {
    __shared__ float t[32][33];
    int n = blockIdx.z;
    src += (size_t)n * sStride;
    dhi += (size_t)n * dStride;
    dlo += (size_t)n * dStride;
    int c0 = blockIdx.x * 32, r0 = blockIdx.y * 32;
    int tx = threadIdx.x, ty = threadIdx.y;
    #pragma unroll
    for (int it = 0; it < 4; it++)
        t[ty + 8 * it][tx] = src[(size_t)(r0 + ty + 8 * it) * HW + c0 + tx];
    __syncthreads();
    #pragma unroll
    for (int it = 0; it < 4; it++) {
        float v = t[tx][ty + 8 * it];
        bf16 h = __float2bfloat16(v);
        size_t o = (size_t)(c0 + ty + 8 * it) * R + r0 + tx;
        dhi[o] = h;
        dlo[o] = __float2bfloat16(v - __bfloat162float(h));
    }
}

// ---------------- QKV projection HMMA ---------------------------------------
__global__ __launch_bounds__(256, 2)
void qkv_hmma() {
    __shared__ __align__(16) bf16 sAh[64 * 32], sAl[64 * 32];
    __shared__ __align__(16) bf16 sBh[128 * 32], sBl[128 * 32];
    int tid = threadIdx.x, lane = tid & 31, wid = tid >> 5;
    int wm = wid & 1, wn = wid >> 1;
    int n = blockIdx.z, m0 = blockIdx.y * 64, l0 = blockIdx.x * 128;

    const bf16* xth = g_xth + (size_t)n * HW * CIN;
    const bf16* xtl = g_xtl + (size_t)n * HW * CIN;
    uint32_t sa_h = smem_u32(sAh), sa_l = smem_u32(sAl);
    uint32_t sb_h = smem_u32(sBh), sb_l = smem_u32(sBl);

    float acc[2][4][4] = {};

    for (int ck = 0; ck < CIN / 32; ck++) {
        {
            int row = tid >> 2, ch = tid & 3;
            uint32_t sw = SW64(row * 64 + ch * 16);
            size_t ga = (size_t)(m0 + row) * CIN + ck * 32 + ch * 8;
            *(float4*)((char*)sAh + sw) = *(const float4*)(const void*)(g_wh + ga);
            *(float4*)((char*)sAl + sw) = *(const float4*)(const void*)(g_wl + ga);
        }
        #pragma unroll
        for (int t = 0; t < 2; t++) {
            int idx = tid + t * 256;
            int row = idx >> 2, ch = idx & 3;
            uint32_t sw = SW64(row * 64 + ch * 16);
            size_t gb = (size_t)(l0 + row) * CIN + ck * 32 + ch * 8;
            *(float4*)((char*)sBh + sw) = *(const float4*)(const void*)(xth + gb);
            *(float4*)((char*)sBl + sw) = *(const float4*)(const void*)(xtl + gb);
        }
        __syncthreads();

        #pragma unroll
        for (int ks = 0; ks < 2; ks++) {
            uint32_t a[2][4], bh[4][2], bl[4][2];
            uint32_t a_off[2];
            #pragma unroll
            for (int mt = 0; mt < 2; mt++) {
                int r = wm * 32 + mt * 16 + (lane & 15);
                a_off[mt] = SW64(r * 64 + ks * 32 + (lane >> 4) * 16);
                LDSM4(a[mt][0], a[mt][1], a[mt][2], a[mt][3], sa_h + a_off[mt]);
            }
            #pragma unroll
            for (int nt = 0; nt < 4; nt++) {
                int r = wn * 32 + nt * 8 + (lane & 7);
                uint32_t sw = SW64(r * 64 + ks * 32 + ((lane >> 3) & 1) * 16);
                LDSM2(bh[nt][0], bh[nt][1], sb_h + sw);
                LDSM2(bl[nt][0], bl[nt][1], sb_l + sw);
            }
            #pragma unroll
            for (int mt = 0; mt < 2; mt++)
                #pragma unroll
                for (int nt = 0; nt < 4; nt++) {
                    MMA16816(acc[mt][nt], a[mt], bh[nt]);
                    MMA16816(acc[mt][nt], a[mt], bl[nt]);
                }
            #pragma unroll
            for (int mt = 0; mt < 2; mt++)
                LDSM4(a[mt][0], a[mt][1], a[mt][2], a[mt][3], sa_l + a_off[mt]);
            #pragma unroll
            for (int mt = 0; mt < 2; mt++)
                #pragma unroll
                for (int nt = 0; nt < 4; nt++)
                    MMA16816(acc[mt][nt], a[mt], bh[nt]);
        }
        __syncthreads();
    }

    #pragma unroll
    for (int mt = 0; mt < 2; mt++) {
        int m = m0 + wm * 32 + mt * 16 + (lane >> 2);
        float* r0p = g_qkv + ((size_t)n * MQKV + m) * HW + l0 + wn * 32 + (lane & 3) * 2;
        float* r1p = r0p + 8 * HW;
        #pragma unroll
        for (int nt = 0; nt < 4; nt++) {
            *(float2*)(r0p + nt * 8) = make_float2(acc[mt][nt][0], acc[mt][nt][1]);
            *(float2*)(r1p + nt * 8) = make_float2(acc[mt][nt][2], acc[mt][nt][3]);
        }
    }
}

// ---------------- Et + exp fused: P[j,i] = exp(kT_j . qT_i) fp16 ------------
__global__ __launch_bounds__(256, 2)
void et_exp_hmma() {
    __shared__ __align__(16) bf16 sAh[128 * 32], sAl[128 * 32];
    __shared__ __align__(16) bf16 sBh[128 * 32], sBl[128 * 32];
    int tid = threadIdx.x, lane = tid & 31, wid = tid >> 5;
    int wm = wid & 1, wn = wid >> 1;
    int n = blockIdx.z, i0 = blockIdx.x * 128, j0 = blockIdx.y * 128;

    const bf16* th = g_qkTh + (size_t)n * HW * 64;
    const bf16* tl = g_qkTl + (size_t)n * HW * 64;
    uint32_t sa_h = smem_u32(sAh), sa_l = smem_u32(sAl);
    uint32_t sb_h = smem_u32(sBh), sb_l = smem_u32(sBl);

    #pragma unroll
    for (int t = 0; t < 2; t++) {
        int idx = tid + t * 256;
        int row = idx >> 2, ch = idx & 3;
        uint32_t sw = SW64(row * 64 + ch * 16);
        *(float4*)((char*)sAh + sw) = *(const float4*)(const void*)(th + (size_t)(j0 + row) * 64 + 32 + ch * 8);
        *(float4*)((char*)sAl + sw) = *(const float4*)(const void*)(tl + (size_t)(j0 + row) * 64 + 32 + ch * 8);
        *(float4*)((char*)sBh + sw) = *(const float4*)(const void*)(th + (size_t)(i0 + row) * 64 + ch * 8);
        *(float4*)((char*)sBl + sw) = *(const float4*)(const void*)(tl + (size_t)(i0 + row) * 64 + ch * 8);
    }
    __syncthreads();

    float acc[4][4][4] = {};
    #pragma unroll
    for (int ks = 0; ks < 2; ks++) {
        uint32_t a[4][4], bh[4][2], bl[4][2];
        uint32_t a_off[4];
        #pragma unroll
        for (int mt = 0; mt < 4; mt++) {
            int r = wm * 64 + mt * 16 + (lane & 15);
            a_off[mt] = SW64(r * 64 + ks * 32 + (lane >> 4) * 16);
            LDSM4(a[mt][0], a[mt][1], a[mt][2], a[mt][3], sa_h + a_off[mt]);
        }
        #pragma unroll
        for (int nt = 0; nt < 4; nt++) {
            int r = wn * 32 + nt * 8 + (lane & 7);
            uint32_t sw = SW64(r * 64 + ks * 32 + ((lane >> 3) & 1) * 16);
            LDSM2(bh[nt][0], bh[nt][1], sb_h + sw);
            LDSM2(bl[nt][0], bl[nt][1], sb_l + sw);
        }
        #pragma unroll
        for (int mt = 0; mt < 4; mt++)
            #pragma unroll
            for (int nt = 0; nt < 4; nt++) {
                MMA16816(acc[mt][nt], a[mt], bh[nt]);
                MMA16816(acc[mt][nt], a[mt], bl[nt]);
            }
        #pragma unroll
        for (int mt = 0; mt < 4; mt++)
            LDSM4(a[mt][0], a[mt][1], a[mt][2], a[mt][3], sa_l + a_off[mt]);
        #pragma unroll
        for (int mt = 0; mt < 4; mt++)
            #pragma unroll
            for (int nt = 0; nt < 4; nt++)
                MMA16816(acc[mt][nt], a[mt], bh[nt]);
    }

    // epilogue: p = exp(e), write fp16, accumulate fp32 column partial sums
    __half* pf = g_pf + (size_t)n * HW * HW;
    float cs[4][2];
    #pragma unroll
    for (int nt = 0; nt < 4; nt++) { cs[nt][0] = 0.0f; cs[nt][1] = 0.0f; }

    #pragma unroll
    for (int mt = 0; mt < 4; mt++) {
        int j = j0 + wm * 64 + mt * 16 + (lane >> 2);
        #pragma unroll
        for (int nt = 0; nt < 4; nt++) {
            int ib = i0 + wn * 32 + nt * 8 + (lane & 3) * 2;
            float p0 = __expf(acc[mt][nt][0]);
            float p1 = __expf(acc[mt][nt][1]);
            float p2 = __expf(acc[mt][nt][2]);
            float p3 = __expf(acc[mt][nt][3]);
            *(__half2*)(pf + (size_t)j * HW + ib) = __floats2half2_rn(p0, p1);
            *(__half2*)(pf + (size_t)(j + 8) * HW + ib) = __floats2half2_rn(p2, p3);
            cs[nt][0] += p0 + p2;
            cs[nt][1] += p1 + p3;
        }
    }
    int seg = blockIdx.y * 2 + wm;
    #pragma unroll
    for (int nt = 0; nt < 4; nt++) {
        #pragma unroll
        for (int c = 0; c < 2; c++) {
            float s = cs[nt][c];
            s += __shfl_xor_sync(0xFFFFFFFFu, s, 4);
            s += __shfl_xor_sync(0xFFFFFFFFu, s, 8);
            s += __shfl_xor_sync(0xFFFFFFFFu, s, 16);
            if ((lane >> 2) == 0) {
                int i = i0 + wn * 32 + nt * 8 + (lane & 3) * 2 + c;
                g_sp[((size_t)n * SSEG + seg) * HW + i] = s;
            }
        }
    }
}

// ---------------- finalize col sums, V'' = V / s * VSCALE (fp16) ------------
__global__ __launch_bounds__(256)
void sum_fin() {
    size_t t = (size_t)blockIdx.x * 256 + threadIdx.x;
    size_t n = t / HW, i = t % HW;
    float s = 0.0f;
    #pragma unroll
    for (int sg = 0; sg < SSEG; sg++)
        s += g_sp[(n * SSEG + sg) * HW + i];
    g_s[t] = s;
}
__global__ __launch_bounds__(256)
void conv_v() {
    size_t idx = (size_t)blockIdx.x * 256 + threadIdx.x;
    size_t n = idx / ((size_t)CV * HW);
    size_t rem = idx % ((size_t)CV * HW);
    size_t r = rem / HW, i = rem % HW;
    float v = g_qkv[((size_t)n * MQKV + 2 * CQK + r) * HW + i];
    g_vf[idx] = __float2half(v / g_s[n * HW + i] * VSCALE);
}

// ---------------- O^T = P @ V''^T  fp16, 1 product, cp.async pipelined ------
// grid (CV/128 v, HW/128 j, NB); BK=64; m-dim j, n-dim v.
#define NCK (HW / 64)
__global__ __launch_bounds__(256, 2)
void mma_ot() {
    __shared__ __align__(16) __half sA[2][128 * 64];
    __shared__ __align__(16) __half sB[2][128 * 64];
    int tid = threadIdx.x, lane = tid & 31, wid = tid >> 5;
    int wm = wid & 1, wn = wid >> 1;
    int n = blockIdx.z, v0 = blockIdx.x * 128, j0 = blockIdx.y * 128;

    const __half* A = g_pf + (size_t)n * HW * HW + (size_t)j0 * HW;
    const __half* B = g_vf + ((size_t)n * CV + v0) * HW;
    uint32_t sa[2] = { smem_u32(sA[0]), smem_u32(sA[1]) };
    uint32_t sb[2] = { smem_u32(sB[0]), smem_u32(sB[1]) };

    // issue loads for chunk ck into buffer buf
    auto issue = [&](int ck, int buf) {
        #pragma unroll
        for (int t = 0; t < 4; t++) {
            int idx = tid + t * 256;            // 0..1023
            int row = idx >> 3, c = idx & 7;
            uint32_t sw = SW128(row * 128 + c * 16);
            size_t go = (size_t)row * HW + (size_t)ck * 64 + c * 8;
            CPA16(sa[buf] + sw, A + go);
            CPA16(sb[buf] + sw, B + go);
        }
    };

    float acc[4][4][4] = {};

    issue(0, 0);
    CPA_COMMIT();
    for (int ck = 0; ck < NCK; ck++) {
        int buf = ck & 1;
        if (ck + 1 < NCK) {
            issue(ck + 1, buf ^ 1);
            CPA_COMMIT();
            CPA_WAIT(1);
        } else {
            CPA_WAIT(0);
        }
        __syncthreads();

        #pragma unroll
        for (int ks = 0; ks < 4; ks++) {
            uint32_t a[4][4], b[4][2];
            #pragma unroll
            for (int mt = 0; mt < 4; mt++) {
                int r = wm * 64 + mt * 16 + (lane & 15);
                uint32_t sw = SW128(r * 128 + ks * 32 + (lane >> 4) * 16);
                LDSM4(a[mt][0], a[mt][1], a[mt][2], a[mt][3], sa[buf] + sw);
            }
            #pragma unroll
            for (int nt = 0; nt < 4; nt++) {
                int r = wn * 32 + nt * 8 + (lane & 7);
                uint32_t sw = SW128(r * 128 + ks * 32 + ((lane >> 3) & 1) * 16);
                LDSM2(b[nt][0], b[nt][1], sb[buf] + sw);
            }
            #pragma unroll
            for (int mt = 0; mt < 4; mt++)
                #pragma unroll
                for (int nt = 0; nt < 4; nt++)
                    MMA16816H(acc[mt][nt], a[mt], b[nt]);
        }
        __syncthreads();
    }

    // epilogue: write O^T[j, v] as bf16 hi/lo
    bf16* oth = g_oth + (size_t)n * HW * CV;
    bf16* otl = g_otl + (size_t)n * HW * CV;
    #pragma unroll
    for (int mt = 0; mt < 4; mt++) {
        int j = j0 + wm * 64 + mt * 16 + (lane >> 2);
        int vb = v0 + wn * 32 + (lane & 3) * 2;
        #pragma unroll
        for (int nt = 0; nt < 4; nt++) {
            float p0 = acc[mt][nt][0], p1 = acc[mt][nt][1];
            float p2 = acc[mt][nt][2], p3 = acc[mt][nt][3];
            bf16 h0 = __float2bfloat16(p0), h1 = __float2bfloat16(p1);
            bf16 h2 = __float2bfloat16(p2), h3 = __float2bfloat16(p3);
            __nv_bfloat162 hv0; hv0.x = h0; hv0.y = h1;
            __nv_bfloat162 hv1; hv1.x = h2; hv1.y = h3;
            __nv_bfloat162 lv0; lv0.x = __float2bfloat16(p0 - __bfloat162float(h0));
                                lv0.y = __float2bfloat16(p1 - __bfloat162float(h1));
            __nv_bfloat162 lv1; lv1.x = __float2bfloat16(p2 - __bfloat162float(h2));
                                lv1.y = __float2bfloat16(p3 - __bfloat162float(h3));
            *(__nv_bfloat162*)(oth + (size_t)j * CV + vb + nt * 8) = hv0;
            *(__nv_bfloat162*)(oth + (size_t)(j + 8) * CV + vb + nt * 8) = hv1;
            *(__nv_bfloat162*)(otl + (size_t)j * CV + vb + nt * 8) = lv0;
            *(__nv_bfloat162*)(otl + (size_t)(j + 8) * CV + vb + nt * 8) = lv1;
        }
    }
}

// ---------------- out = (gamma/VSCALE) * Wo @ O ------------------------------
__global__ __launch_bounds__(256, 2)
void wo_hmma(float* __restrict__ out, const float* __restrict__ gammaPtr) {
    __shared__ __align__(16) bf16 sAh[128 * 32], sAl[128 * 32];
    __shared__ __align__(16) bf16 sBh[128 * 32], sBl[128 * 32];
    int tid = threadIdx.x, lane = tid & 31, wid = tid >> 5;
    int wm = wid & 1, wn = wid >> 1;
    int n = blockIdx.z, o0 = blockIdx.y * 128, l0 = blockIdx.x * 128;

    const bf16* oth = g_oth + (size_t)n * HW * CV;
    const bf16* otl = g_otl + (size_t)n * HW * CV;
    uint32_t sa_h = smem_u32(sAh), sa_l = smem_u32(sAl);
    uint32_t sb_h = smem_u32(sBh), sb_l = smem_u32(sBl);

    float acc[4][4][4] = {};

    for (int ck = 0; ck < CV / 32; ck++) {
        #pragma unroll
        for (int t = 0; t < 2; t++) {
            int idx = tid + t * 256;
            int row = idx >> 2, ch = idx & 3;
            uint32_t sw = SW64(row * 64 + ch * 16);
            size_t ga = (size_t)(o0 + row) * CV + ck * 32 + ch * 8;
            size_t gb = (size_t)(l0 + row) * CV + ck * 32 + ch * 8;
            *(float4*)((char*)sAh + sw) = *(const float4*)(const void*)(g_woh + ga);
            *(float4*)((char*)sAl + sw) = *(const float4*)(const void*)(g_wol + ga);
            *(float4*)((char*)sBh + sw) = *(const float4*)(const void*)(oth + gb);
            *(float4*)((char*)sBl + sw) = *(const float4*)(const void*)(otl + gb);
        }
        __syncthreads();

        #pragma unroll
        for (int ks = 0; ks < 2; ks++) {
            uint32_t a[4][4], bh[4][2], bl[4][2];
            uint32_t a_off[4];
            #pragma unroll
            for (int mt = 0; mt < 4; mt++) {
                int r = wm * 64 + mt * 16 + (lane & 15);
                a_off[mt] = SW64(r * 64 + ks * 32 + (lane >> 4) * 16);
                LDSM4(a[mt][0], a[mt][1], a[mt][2], a[mt][3], sa_h + a_off[mt]);
            }
            #pragma unroll
            for (int nt = 0; nt < 4; nt++) {
                int r = wn * 32 + nt * 8 + (lane & 7);
                uint32_t sw = SW64(r * 64 + ks * 32 + ((lane >> 3) & 1) * 16);
                LDSM2(bh[nt][0], bh[nt][1], sb_h + sw);
                LDSM2(bl[nt][0], bl[nt][1], sb_l + sw);
            }
            #pragma unroll
            for (int mt = 0; mt < 4; mt++)
                #pragma unroll
                for (int nt = 0; nt < 4; nt++) {
                    MMA16816(acc[mt][nt], a[mt], bh[nt]);
                    MMA16816(acc[mt][nt], a[mt], bl[nt]);
                }
            #pragma unroll
            for (int mt = 0; mt < 4; mt++)
                LDSM4(a[mt][0], a[mt][1], a[mt][2], a[mt][3], sa_l + a_off[mt]);
            #pragma unroll
            for (int mt = 0; mt < 4; mt++)
                #pragma unroll
                for (int nt = 0; nt < 4; nt++)
                    MMA16816(acc[mt][nt], a[mt], bh[nt]);
        }
        __syncthreads();
    }

    float gamma = *gammaPtr * (1.0f / VSCALE);
    #pragma unroll
    for (int mt = 0; mt < 4; mt++) {
        int o = o0 + wm * 64 + mt * 16 + (lane >> 2);
        float* r0p = out + ((size_t)n * CIN + o) * HW + l0 + wn * 32 + (lane & 3) * 2;
        float* r1p = r0p + 8 * HW;
        #pragma unroll
        for (int nt = 0; nt < 4; nt++) {
            *(float2*)(r0p + nt * 8) = make_float2(gamma * acc[mt][nt][0], gamma * acc[mt][nt][1]);
            *(float2*)(r1p + nt * 8) = make_float2(gamma * acc[mt][nt][2], gamma * acc[mt][nt][3]);
        }
    }
}

// ---------------- launch ----------------------------------------------------
extern "C" void kernel_launch(void* const* d_in, const int* in_sizes, int n_in,
                              void* d_out, int out_size) {
    const float* x     = (const float*)d_in[0];
    const float* Wq    = (const float*)d_in[1];
    const float* Wk    = (const float*)d_in[2];
    const float* Wv    = (const float*)d_in[3];
    const float* Wo    = (const float*)d_in[4];
    const float* gamma = (const float*)d_in[5];
    float* out = (float*)d_out;

    float* qkv = nullptr; cudaGetSymbolAddress((void**)&qkv, g_qkv);
    bf16* xth = nullptr;  cudaGetSymbolAddress((void**)&xth, g_xth);
    bf16* xtl = nullptr;  cudaGetSymbolAddress((void**)&xtl, g_xtl);
    bf16* qkh = nullptr;  cudaGetSymbolAddress((void**)&qkh, g_qkTh);
    bf16* qkl = nullptr;  cudaGetSymbolAddress((void**)&qkl, g_qkTl);

    // 1. split weights
    split_w<<<(MQKV * CIN + CIN * CV + 255) / 256, 256>>>(Wq, Wk, Wv, Wo);
    // 2. xT split
    trsp<<<dim3(HW / 32, CIN / 32, NB), dim3(32, 8)>>>(
        x, xth, xtl, CIN, (size_t)CIN * HW, (size_t)HW * CIN);
    // 3. QKV projection
    qkv_hmma<<<dim3(HW / 128, MQKV / 64, NB), 256>>>();
    // 4. qT/kT split
    trsp<<<dim3(HW / 32, 2, NB), dim3(32, 8)>>>(
        qkv, qkh, qkl, 64, (size_t)MQKV * HW, (size_t)HW * 64);
    // 5. Et + exp fused -> P fp16, partial col sums
    et_exp_hmma<<<dim3(HW / 128, HW / 128, NB), 256>>>();
    // 6. finalize sums; V'' = V / s * VSCALE fp16
    sum_fin<<<(NB * HW) / 256, 256>>>();
    conv_v<<<(NB * CV * HW) / 256, 256>>>();
    // 7. O^T = P @ V''^T (fp16, 1 product, cp.async pipeline)
    mma_ot<<<dim3(CV / 128, HW / 128, NB), 256>>>();
    // 8. out = (gamma/VSCALE) * Wo @ O
    wo_hmma<<<dim3(HW / 128, CIN / 128, NB), 256>>>(out, gamma);
}

// round 11
// speedup vs baseline: 2.2195x; 1.0729x over previous
#include <cuda_runtime.h>
#include <cuda_bf16.h>
#include <cuda_fp16.h>
#include <cstdint>
#include <cstddef>

#define HW   4096
#define CIN  256
#define CQK  32
#define CV   256
#define NB   8
#define MQKV 320
#define SSEG 64
#define VSCALE 1024.0f

typedef __nv_bfloat16 bf16;

// ---------------- scratch -----------------------------------------------
__device__ bf16  g_wh[MQKV * CIN];
__device__ bf16  g_wl[MQKV * CIN];
__device__ bf16  g_woh[CIN * CV];
__device__ bf16  g_wol[CIN * CV];
__device__ bf16  g_xth[(size_t)NB * HW * CIN];
__device__ bf16  g_xtl[(size_t)NB * HW * CIN];
__device__ float g_qkv[(size_t)NB * MQKV * HW];
__device__ __half g_qkT[(size_t)NB * HW * 64];        // fp16 [l][0:32]=qT,[32:64]=kT
__device__ float g_sp[(size_t)NB * SSEG * HW];
__device__ float g_s[(size_t)NB * HW];
__device__ __half g_pf[(size_t)NB * HW * HW];         // P=exp(E) fp16 [j,i]
__device__ __half g_vf[(size_t)NB * CV * HW];         // (V/s)*1024 fp16 [v,i]
__device__ bf16  g_oth[(size_t)NB * HW * CV];         // O^T hi [l, v]
__device__ bf16  g_otl[(size_t)NB * HW * CV];

// ---------------- helpers -------------------------------------------------
static __device__ __forceinline__ uint32_t smem_u32(const void* p) {
    uint32_t a;
    asm("{ .reg .u64 t; cvta.to.shared.u64 t, %1; cvt.u32.u64 %0, t; }" : "=r"(a) : "l"(p));
    return a;
}
#define SW64(x)  ((x) ^ (((x) >> 3) & 0x30))
#define SW128(x) ((x) ^ (((x) >> 3) & 0x70))
#define LDSM4(r0, r1, r2, r3, addr) \
    asm volatile("ldmatrix.sync.aligned.m8n8.x4.shared.b16 {%0,%1,%2,%3}, [%4];" \
                 : "=r"(r0), "=r"(r1), "=r"(r2), "=r"(r3) : "r"(addr))
#define LDSM2(r0, r1, addr) \
    asm volatile("ldmatrix.sync.aligned.m8n8.x2.shared.b16 {%0,%1}, [%2];" \
                 : "=r"(r0), "=r"(r1) : "r"(addr))
#define MMA16816(c, a, b) \
    asm volatile("mma.sync.aligned.m16n8k16.row.col.f32.bf16.bf16.f32 " \
                 "{%0,%1,%2,%3}, {%4,%5,%6,%7}, {%8,%9}, {%0,%1,%2,%3};" \
                 : "+f"((c)[0]), "+f"((c)[1]), "+f"((c)[2]), "+f"((c)[3]) \
                 : "r"((a)[0]), "r"((a)[1]), "r"((a)[2]), "r"((a)[3]), \
                   "r"((b)[0]), "r"((b)[1]))
#define MMA16816H(c, a, b) \
    asm volatile("mma.sync.aligned.m16n8k16.row.col.f32.f16.f16.f32 " \
                 "{%0,%1,%2,%3}, {%4,%5,%6,%7}, {%8,%9}, {%0,%1,%2,%3};" \
                 : "+f"((c)[0]), "+f"((c)[1]), "+f"((c)[2]), "+f"((c)[3]) \
                 : "r"((a)[0]), "r"((a)[1]), "r"((a)[2]), "r"((a)[3]), \
                   "r"((b)[0]), "r"((b)[1]))
#define CPA16(saddr, gptr) \
    asm volatile("cp.async.cg.shared.global [%0], [%1], 16;" :: "r"(saddr), "l"(gptr))
#define CPA_COMMIT() asm volatile("cp.async.commit_group;")
#define CPA_WAIT(N)  asm volatile("cp.async.wait_group %0;" :: "n"(N))

// ---------------- weight split --------------------------------------------
__global__ void split_w(const float* __restrict__ Wq, const float* __restrict__ Wk,
                        const float* __restrict__ Wv, const float* __restrict__ Wo) {
    int i = blockIdx.x * 256 + threadIdx.x;
    if (i < MQKV * CIN) {
        float v = (i < CQK * CIN) ? Wq[i]
                : (i < 2 * CQK * CIN) ? Wk[i - CQK * CIN]
                : Wv[i - 2 * CQK * CIN];
        bf16 h = __float2bfloat16(v);
        g_wh[i] = h;
        g_wl[i] = __float2bfloat16(v - __bfloat162float(h));
    } else {
        int j = i - MQKV * CIN;
        if (j < CIN * CV) {
            float v = Wo[j];
            bf16 h = __float2bfloat16(v);
            g_woh[j] = h;
            g_wol[j] = __float2bfloat16(v - __bfloat162float(h));
        }
    }
}

// ---------------- transpose + bf16 split ------------------------------------
__global__ __launch_bounds__(256)
void trsp(const float* __restrict__ src, bf16* __restrict__ dhi, bf16* __restrict__ dlo,
          int R, size_t sStride, size_t dStride) {
    __shared__ float t[32][33];
    int n = blockIdx.z;
    src += (size_t)n * sStride;
    dhi += (size_t)n * dStride;
    dlo += (size_t)n * dStride;
    int c0 = blockIdx.x * 32, r0 = blockIdx.y * 32;
    int tx = threadIdx.x, ty = threadIdx.y;
    #pragma unroll
    for (int it = 0; it < 4; it++)
        t[ty + 8 * it][tx] = src[(size_t)(r0 + ty + 8 * it) * HW + c0 + tx];
    __syncthreads();
    #pragma unroll
    for (int it = 0; it < 4; it++) {
        float v = t[tx][ty + 8 * it];
        bf16 h = __float2bfloat16(v);
        size_t o = (size_t)(c0 + ty + 8 * it) * R + r0 + tx;
        dhi[o] = h;
        dlo[o] = __float2bfloat16(v - __bfloat162float(h));
    }
}

// ---------------- transpose -> single fp16: src[R,HW] -> dst[HW,R] ----------
__global__ __launch_bounds__(256)
void trsp_h(const float* __restrict__ src, __half* __restrict__ dst,
            int R, size_t sStride, size_t dStride) {
    __shared__ float t[32][33];
    int n = blockIdx.z;
    src += (size_t)n * sStride;
    dst += (size_t)n * dStride;
    int c0 = blockIdx.x * 32, r0 = blockIdx.y * 32;
    int tx = threadIdx.x, ty = threadIdx.y;
    #pragma unroll
    for (int it = 0; it < 4; it++)
        t[ty + 8 * it][tx] = src[(size_t)(r0 + ty + 8 * it) * HW + c0 + tx];
    __syncthreads();
    #pragma unroll
    for (int it = 0; it < 4; it++)
        dst[(size_t)(c0 + ty + 8 * it) * R + r0 + tx] = __float2half(t[tx][ty + 8 * it]);
}

// ---------------- QKV projection HMMA (bf16 3-product) ----------------------
__global__ __launch_bounds__(256, 2)
void qkv_hmma() {
    __shared__ __align__(16) bf16 sAh[64 * 32], sAl[64 * 32];
    __shared__ __align__(16) bf16 sBh[128 * 32], sBl[128 * 32];
    int tid = threadIdx.x, lane = tid & 31, wid = tid >> 5;
    int wm = wid & 1, wn = wid >> 1;
    int n = blockIdx.z, m0 = blockIdx.y * 64, l0 = blockIdx.x * 128;

    const bf16* xth = g_xth + (size_t)n * HW * CIN;
    const bf16* xtl = g_xtl + (size_t)n * HW * CIN;
    uint32_t sa_h = smem_u32(sAh), sa_l = smem_u32(sAl);
    uint32_t sb_h = smem_u32(sBh), sb_l = smem_u32(sBl);

    float acc[2][4][4] = {};

    for (int ck = 0; ck < CIN / 32; ck++) {
        {
            int row = tid >> 2, ch = tid & 3;
            uint32_t sw = SW64(row * 64 + ch * 16);
            size_t ga = (size_t)(m0 + row) * CIN + ck * 32 + ch * 8;
            *(float4*)((char*)sAh + sw) = *(const float4*)(const void*)(g_wh + ga);
            *(float4*)((char*)sAl + sw) = *(const float4*)(const void*)(g_wl + ga);
        }
        #pragma unroll
        for (int t = 0; t < 2; t++) {
            int idx = tid + t * 256;
            int row = idx >> 2, ch = idx & 3;
            uint32_t sw = SW64(row * 64 + ch * 16);
            size_t gb = (size_t)(l0 + row) * CIN + ck * 32 + ch * 8;
            *(float4*)((char*)sBh + sw) = *(const float4*)(const void*)(xth + gb);
            *(float4*)((char*)sBl + sw) = *(const float4*)(const void*)(xtl + gb);
        }
        __syncthreads();

        #pragma unroll
        for (int ks = 0; ks < 2; ks++) {
            uint32_t a[2][4], bh[4][2], bl[4][2];
            uint32_t a_off[2];
            #pragma unroll
            for (int mt = 0; mt < 2; mt++) {
                int r = wm * 32 + mt * 16 + (lane & 15);
                a_off[mt] = SW64(r * 64 + ks * 32 + (lane >> 4) * 16);
                LDSM4(a[mt][0], a[mt][1], a[mt][2], a[mt][3], sa_h + a_off[mt]);
            }
            #pragma unroll
            for (int nt = 0; nt < 4; nt++) {
                int r = wn * 32 + nt * 8 + (lane & 7);
                uint32_t sw = SW64(r * 64 + ks * 32 + ((lane >> 3) & 1) * 16);
                LDSM2(bh[nt][0], bh[nt][1], sb_h + sw);
                LDSM2(bl[nt][0], bl[nt][1], sb_l + sw);
            }
            #pragma unroll
            for (int mt = 0; mt < 2; mt++)
                #pragma unroll
                for (int nt = 0; nt < 4; nt++) {
                    MMA16816(acc[mt][nt], a[mt], bh[nt]);
                    MMA16816(acc[mt][nt], a[mt], bl[nt]);
                }
            #pragma unroll
            for (int mt = 0; mt < 2; mt++)
                LDSM4(a[mt][0], a[mt][1], a[mt][2], a[mt][3], sa_l + a_off[mt]);
            #pragma unroll
            for (int mt = 0; mt < 2; mt++)
                #pragma unroll
                for (int nt = 0; nt < 4; nt++)
                    MMA16816(acc[mt][nt], a[mt], bh[nt]);
        }
        __syncthreads();
    }

    #pragma unroll
    for (int mt = 0; mt < 2; mt++) {
        int m = m0 + wm * 32 + mt * 16 + (lane >> 2);
        float* r0p = g_qkv + ((size_t)n * MQKV + m) * HW + l0 + wn * 32 + (lane & 3) * 2;
        float* r1p = r0p + 8 * HW;
        #pragma unroll
        for (int nt = 0; nt < 4; nt++) {
            *(float2*)(r0p + nt * 8) = make_float2(acc[mt][nt][0], acc[mt][nt][1]);
            *(float2*)(r1p + nt * 8) = make_float2(acc[mt][nt][2], acc[mt][nt][3]);
        }
    }
}

// ---------------- Et + exp fused: single fp16 product -----------------------
// grid (HW/128 i, HW/128 j, NB); 8 warps (2x4), warp 64x32.
__global__ __launch_bounds__(256, 2)
void et_exp_hmma() {
    __shared__ __align__(16) __half sA[128 * 32];   // kT tile [j,32]
    __shared__ __align__(16) __half sB[128 * 32];   // qT tile [i,32]
    int tid = threadIdx.x, lane = tid & 31, wid = tid >> 5;
    int wm = wid & 1, wn = wid >> 1;
    int n = blockIdx.z, i0 = blockIdx.x * 128, j0 = blockIdx.y * 128;

    const __half* t64 = g_qkT + (size_t)n * HW * 64;
    uint32_t sa = smem_u32(sA), sb = smem_u32(sB);

    #pragma unroll
    for (int t = 0; t < 2; t++) {
        int idx = tid + t * 256;
        int row = idx >> 2, ch = idx & 3;
        uint32_t sw = SW64(row * 64 + ch * 16);
        *(float4*)((char*)sA + sw) = *(const float4*)(const void*)(t64 + (size_t)(j0 + row) * 64 + 32 + ch * 8);
        *(float4*)((char*)sB + sw) = *(const float4*)(const void*)(t64 + (size_t)(i0 + row) * 64 + ch * 8);
    }
    __syncthreads();

    float acc[4][4][4] = {};
    #pragma unroll
    for (int ks = 0; ks < 2; ks++) {
        uint32_t a[4][4], b[4][2];
        #pragma unroll
        for (int mt = 0; mt < 4; mt++) {
            int r = wm * 64 + mt * 16 + (lane & 15);
            uint32_t sw = SW64(r * 64 + ks * 32 + (lane >> 4) * 16);
            LDSM4(a[mt][0], a[mt][1], a[mt][2], a[mt][3], sa + sw);
        }
        #pragma unroll
        for (int nt = 0; nt < 4; nt++) {
            int r = wn * 32 + nt * 8 + (lane & 7);
            uint32_t sw = SW64(r * 64 + ks * 32 + ((lane >> 3) & 1) * 16);
            LDSM2(b[nt][0], b[nt][1], sb + sw);
        }
        #pragma unroll
        for (int mt = 0; mt < 4; mt++)
            #pragma unroll
            for (int nt = 0; nt < 4; nt++)
                MMA16816H(acc[mt][nt], a[mt], b[nt]);
    }

    // epilogue: p = exp(e) fp16, fp32 column partial sums
    __half* pf = g_pf + (size_t)n * HW * HW;
    float cs[4][2];
    #pragma unroll
    for (int nt = 0; nt < 4; nt++) { cs[nt][0] = 0.0f; cs[nt][1] = 0.0f; }

    #pragma unroll
    for (int mt = 0; mt < 4; mt++) {
        int j = j0 + wm * 64 + mt * 16 + (lane >> 2);
        #pragma unroll
        for (int nt = 0; nt < 4; nt++) {
            int ib = i0 + wn * 32 + nt * 8 + (lane & 3) * 2;
            float p0 = __expf(acc[mt][nt][0]);
            float p1 = __expf(acc[mt][nt][1]);
            float p2 = __expf(acc[mt][nt][2]);
            float p3 = __expf(acc[mt][nt][3]);
            *(__half2*)(pf + (size_t)j * HW + ib) = __floats2half2_rn(p0, p1);
            *(__half2*)(pf + (size_t)(j + 8) * HW + ib) = __floats2half2_rn(p2, p3);
            cs[nt][0] += p0 + p2;
            cs[nt][1] += p1 + p3;
        }
    }
    int seg = blockIdx.y * 2 + wm;
    #pragma unroll
    for (int nt = 0; nt < 4; nt++) {
        #pragma unroll
        for (int c = 0; c < 2; c++) {
            float s = cs[nt][c];
            s += __shfl_xor_sync(0xFFFFFFFFu, s, 4);
            s += __shfl_xor_sync(0xFFFFFFFFu, s, 8);
            s += __shfl_xor_sync(0xFFFFFFFFu, s, 16);
            if ((lane >> 2) == 0) {
                int i = i0 + wn * 32 + nt * 8 + (lane & 3) * 2 + c;
                g_sp[((size_t)n * SSEG + seg) * HW + i] = s;
            }
        }
    }
}

// ---------------- finalize col sums, V'' = V / s * VSCALE (fp16) ------------
__global__ __launch_bounds__(256)
void sum_fin() {
    size_t t = (size_t)blockIdx.x * 256 + threadIdx.x;
    size_t n = t / HW, i = t % HW;
    float s = 0.0f;
    #pragma unroll
    for (int sg = 0; sg < SSEG; sg++)
        s += g_sp[(n * SSEG + sg) * HW + i];
    g_s[t] = s;
}
__global__ __launch_bounds__(256)
void conv_v() {
    size_t idx = (size_t)blockIdx.x * 256 + threadIdx.x;
    size_t n = idx / ((size_t)CV * HW);
    size_t rem = idx % ((size_t)CV * HW);
    size_t r = rem / HW, i = rem % HW;
    float v = g_qkv[((size_t)n * MQKV + 2 * CQK + r) * HW + i];
    g_vf[idx] = __float2half(v / g_s[n * HW + i] * VSCALE);
}

// ---------------- O^T = P @ V''^T  fp16, cp.async pipelined -----------------
#define NCK (HW / 64)
__global__ __launch_bounds__(256, 2)
void mma_ot() {
    __shared__ __align__(16) __half sA[2][128 * 64];
    __shared__ __align__(16) __half sB[2][128 * 64];
    int tid = threadIdx.x, lane = tid & 31, wid = tid >> 5;
    int wm = wid & 1, wn = wid >> 1;
    int n = blockIdx.z, v0 = blockIdx.x * 128, j0 = blockIdx.y * 128;

    const __half* A = g_pf + (size_t)n * HW * HW + (size_t)j0 * HW;
    const __half* B = g_vf + ((size_t)n * CV + v0) * HW;
    uint32_t sa[2] = { smem_u32(sA[0]), smem_u32(sA[1]) };
    uint32_t sb[2] = { smem_u32(sB[0]), smem_u32(sB[1]) };

    auto issue = [&](int ck, int buf) {
        #pragma unroll
        for (int t = 0; t < 4; t++) {
            int idx = tid + t * 256;
            int row = idx >> 3, c = idx & 7;
            uint32_t sw = SW128(row * 128 + c * 16);
            size_t go = (size_t)row * HW + (size_t)ck * 64 + c * 8;
            CPA16(sa[buf] + sw, A + go);
            CPA16(sb[buf] + sw, B + go);
        }
    };

    float acc[4][4][4] = {};

    issue(0, 0);
    CPA_COMMIT();
    for (int ck = 0; ck < NCK; ck++) {
        int buf = ck & 1;
        if (ck + 1 < NCK) {
            issue(ck + 1, buf ^ 1);
            CPA_COMMIT();
            CPA_WAIT(1);
        } else {
            CPA_WAIT(0);
        }
        __syncthreads();

        #pragma unroll
        for (int ks = 0; ks < 4; ks++) {
            uint32_t a[4][4], b[4][2];
            #pragma unroll
            for (int mt = 0; mt < 4; mt++) {
                int r = wm * 64 + mt * 16 + (lane & 15);
                uint32_t sw = SW128(r * 128 + ks * 32 + (lane >> 4) * 16);
                LDSM4(a[mt][0], a[mt][1], a[mt][2], a[mt][3], sa[buf] + sw);
            }
            #pragma unroll
            for (int nt = 0; nt < 4; nt++) {
                int r = wn * 32 + nt * 8 + (lane & 7);
                uint32_t sw = SW128(r * 128 + ks * 32 + ((lane >> 3) & 1) * 16);
                LDSM2(b[nt][0], b[nt][1], sb[buf] + sw);
            }
            #pragma unroll
            for (int mt = 0; mt < 4; mt++)
                #pragma unroll
                for (int nt = 0; nt < 4; nt++)
                    MMA16816H(acc[mt][nt], a[mt], b[nt]);
        }
        __syncthreads();
    }

    bf16* oth = g_oth + (size_t)n * HW * CV;
    bf16* otl = g_otl + (size_t)n * HW * CV;
    #pragma unroll
    for (int mt = 0; mt < 4; mt++) {
        int j = j0 + wm * 64 + mt * 16 + (lane >> 2);
        int vb = v0 + wn * 32 + (lane & 3) * 2;
        #pragma unroll
        for (int nt = 0; nt < 4; nt++) {
            float p0 = acc[mt][nt][0], p1 = acc[mt][nt][1];
            float p2 = acc[mt][nt][2], p3 = acc[mt][nt][3];
            bf16 h0 = __float2bfloat16(p0), h1 = __float2bfloat16(p1);
            bf16 h2 = __float2bfloat16(p2), h3 = __float2bfloat16(p3);
            __nv_bfloat162 hv0; hv0.x = h0; hv0.y = h1;
            __nv_bfloat162 hv1; hv1.x = h2; hv1.y = h3;
            __nv_bfloat162 lv0; lv0.x = __float2bfloat16(p0 - __bfloat162float(h0));
                                lv0.y = __float2bfloat16(p1 - __bfloat162float(h1));
            __nv_bfloat162 lv1; lv1.x = __float2bfloat16(p2 - __bfloat162float(h2));
                                lv1.y = __float2bfloat16(p3 - __bfloat162float(h3));
            *(__nv_bfloat162*)(oth + (size_t)j * CV + vb + nt * 8) = hv0;
            *(__nv_bfloat162*)(oth + (size_t)(j + 8) * CV + vb + nt * 8) = hv1;
            *(__nv_bfloat162*)(otl + (size_t)j * CV + vb + nt * 8) = lv0;
            *(__nv_bfloat162*)(otl + (size_t)(j + 8) * CV + vb + nt * 8) = lv1;
        }
    }
}

// ---------------- out = (gamma/VSCALE) * Wo @ O ------------------------------
__global__ __launch_bounds__(256, 2)
void wo_hmma(float* __restrict__ out, const float* __restrict__ gammaPtr) {
    __shared__ __align__(16) bf16 sAh[128 * 32], sAl[128 * 32];
    __shared__ __align__(16) bf16 sBh[128 * 32], sBl[128 * 32];
    int tid = threadIdx.x, lane = tid & 31, wid = tid >> 5;
    int wm = wid & 1, wn = wid >> 1;
    int n = blockIdx.z, o0 = blockIdx.y * 128, l0 = blockIdx.x * 128;

    const bf16* oth = g_oth + (size_t)n * HW * CV;
    const bf16* otl = g_otl + (size_t)n * HW * CV;
    uint32_t sa_h = smem_u32(sAh), sa_l = smem_u32(sAl);
    uint32_t sb_h = smem_u32(sBh), sb_l = smem_u32(sBl);

    float acc[4][4][4] = {};

    for (int ck = 0; ck < CV / 32; ck++) {
        #pragma unroll
        for (int t = 0; t < 2; t++) {
            int idx = tid + t * 256;
            int row = idx >> 2, ch = idx & 3;
            uint32_t sw = SW64(row * 64 + ch * 16);
            size_t ga = (size_t)(o0 + row) * CV + ck * 32 + ch * 8;
            size_t gb = (size_t)(l0 + row) * CV + ck * 32 + ch * 8;
            *(float4*)((char*)sAh + sw) = *(const float4*)(const void*)(g_woh + ga);
            *(float4*)((char*)sAl + sw) = *(const float4*)(const void*)(g_wol + ga);
            *(float4*)((char*)sBh + sw) = *(const float4*)(const void*)(oth + gb);
            *(float4*)((char*)sBl + sw) = *(const float4*)(const void*)(otl + gb);
        }
        __syncthreads();

        #pragma unroll
        for (int ks = 0; ks < 2; ks++) {
            uint32_t a[4][4], bh[4][2], bl[4][2];
            uint32_t a_off[4];
            #pragma unroll
            for (int mt = 0; mt < 4; mt++) {
                int r = wm * 64 + mt * 16 + (lane & 15);
                a_off[mt] = SW64(r * 64 + ks * 32 + (lane >> 4) * 16);
                LDSM4(a[mt][0], a[mt][1], a[mt][2], a[mt][3], sa_h + a_off[mt]);
            }
            #pragma unroll
            for (int nt = 0; nt < 4; nt++) {
                int r = wn * 32 + nt * 8 + (lane & 7);
                uint32_t sw = SW64(r * 64 + ks * 32 + ((lane >> 3) & 1) * 16);
                LDSM2(bh[nt][0], bh[nt][1], sb_h + sw);
                LDSM2(bl[nt][0], bl[nt][1], sb_l + sw);
            }
            #pragma unroll
            for (int mt = 0; mt < 4; mt++)
                #pragma unroll
                for (int nt = 0; nt < 4; nt++) {
                    MMA16816(acc[mt][nt], a[mt], bh[nt]);
                    MMA16816(acc[mt][nt], a[mt], bl[nt]);
                }
            #pragma unroll
            for (int mt = 0; mt < 4; mt++)
                LDSM4(a[mt][0], a[mt][1], a[mt][2], a[mt][3], sa_l + a_off[mt]);
            #pragma unroll
            for (int mt = 0; mt < 4; mt++)
                #pragma unroll
                for (int nt = 0; nt < 4; nt++)
                    MMA16816(acc[mt][nt], a[mt], bh[nt]);
        }
        __syncthreads();
    }

    float gamma = *gammaPtr * (1.0f / VSCALE);
    #pragma unroll
    for (int mt = 0; mt < 4; mt++) {
        int o = o0 + wm * 64 + mt * 16 + (lane >> 2);
        float* r0p = out + ((size_t)n * CIN + o) * HW + l0 + wn * 32 + (lane & 3) * 2;
        float* r1p = r0p + 8 * HW;
        #pragma unroll
        for (int nt = 0; nt < 4; nt++) {
            *(float2*)(r0p + nt * 8) = make_float2(gamma * acc[mt][nt][0], gamma * acc[mt][nt][1]);
            *(float2*)(r1p + nt * 8) = make_float2(gamma * acc[mt][nt][2], gamma * acc[mt][nt][3]);
        }
    }
}

// ---------------- launch ----------------------------------------------------
extern "C" void kernel_launch(void* const* d_in, const int* in_sizes, int n_in,
                              void* d_out, int out_size) {
    const float* x     = (const float*)d_in[0];
    const float* Wq    = (const float*)d_in[1];
    const float* Wk    = (const float*)d_in[2];
    const float* Wv    = (const float*)d_in[3];
    const float* Wo    = (const float*)d_in[4];
    const float* gamma = (const float*)d_in[5];
    float* out = (float*)d_out;

    float* qkv = nullptr;  cudaGetSymbolAddress((void**)&qkv, g_qkv);
    bf16* xth = nullptr;   cudaGetSymbolAddress((void**)&xth, g_xth);
    bf16* xtl = nullptr;   cudaGetSymbolAddress((void**)&xtl, g_xtl);
    __half* qkT = nullptr; cudaGetSymbolAddress((void**)&qkT, g_qkT);

    // 1. split weights
    split_w<<<(MQKV * CIN + CIN * CV + 255) / 256, 256>>>(Wq, Wk, Wv, Wo);
    // 2. xT split (bf16 hi/lo)
    trsp<<<dim3(HW / 32, CIN / 32, NB), dim3(32, 8)>>>(
        x, xth, xtl, CIN, (size_t)CIN * HW, (size_t)HW * CIN);
    // 3. QKV projection
    qkv_hmma<<<dim3(HW / 128, MQKV / 64, NB), 256>>>();
    // 4. qT/kT -> fp16 single
    trsp_h<<<dim3(HW / 32, 2, NB), dim3(32, 8)>>>(
        qkv, qkT, 64, (size_t)MQKV * HW, (size_t)HW * 64);
    // 5. Et + exp fused (single fp16 product) -> P fp16, partial col sums
    et_exp_hmma<<<dim3(HW / 128, HW / 128, NB), 256>>>();
    // 6. finalize sums; V'' fp16
    sum_fin<<<(NB * HW) / 256, 256>>>();
    conv_v<<<(NB * CV * HW) / 256, 256>>>();
    // 7. O^T = P @ V''^T (fp16, pipelined)
    mma_ot<<<dim3(CV / 128, HW / 128, NB), 256>>>();
    // 8. out = (gamma/VSCALE) * Wo @ O
    wo_hmma<<<dim3(HW / 128, CIN / 128, NB), 256>>>(out, gamma);
}

// round 12
// speedup vs baseline: 2.4385x; 1.0987x over previous
#include <cuda_runtime.h>
#include <cuda_bf16.h>
#include <cuda_fp16.h>
#include <cstdint>
#include <cstddef>

#define HW   4096
#define CIN  256
#define CQK  32
#define CV   256
#define NB   8
#define MQKV 320
#define SSEG 64
#define VSCALE 1024.0f

typedef __nv_bfloat16 bf16;

// ---------------- scratch -----------------------------------------------
__device__ __half g_wf[MQKV * CIN];                   // qkv weights fp16
__device__ bf16  g_woh[CIN * CV];
__device__ bf16  g_wol[CIN * CV];
__device__ __half g_xtf[(size_t)NB * HW * CIN];       // x^T fp16 [l, c]
__device__ float g_qkv[(size_t)NB * MQKV * HW];
__device__ __half g_qkT[(size_t)NB * HW * 64];        // fp16 [l][0:32]=qT,[32:64]=kT
__device__ float g_sp[(size_t)NB * SSEG * HW];
__device__ float g_s[(size_t)NB * HW];
__device__ __half g_pf[(size_t)NB * HW * HW];         // P=exp(E) fp16 [j,i]
__device__ __half g_vf[(size_t)NB * CV * HW];         // (V/s)*1024 fp16 [v,i]
__device__ bf16  g_oth[(size_t)NB * HW * CV];         // O^T hi [l, v]
__device__ bf16  g_otl[(size_t)NB * HW * CV];

// ---------------- helpers -------------------------------------------------
static __device__ __forceinline__ uint32_t smem_u32(const void* p) {
    uint32_t a;
    asm("{ .reg .u64 t; cvta.to.shared.u64 t, %1; cvt.u32.u64 %0, t; }" : "=r"(a) : "l"(p));
    return a;
}
#define SW64(x)  ((x) ^ (((x) >> 3) & 0x30))
#define SW128(x) ((x) ^ (((x) >> 3) & 0x70))
#define LDSM4(r0, r1, r2, r3, addr) \
    asm volatile("ldmatrix.sync.aligned.m8n8.x4.shared.b16 {%0,%1,%2,%3}, [%4];" \
                 : "=r"(r0), "=r"(r1), "=r"(r2), "=r"(r3) : "r"(addr))
#define LDSM2(r0, r1, addr) \
    asm volatile("ldmatrix.sync.aligned.m8n8.x2.shared.b16 {%0,%1}, [%2];" \
                 : "=r"(r0), "=r"(r1) : "r"(addr))
#define MMA16816(c, a, b) \
    asm volatile("mma.sync.aligned.m16n8k16.row.col.f32.bf16.bf16.f32 " \
                 "{%0,%1,%2,%3}, {%4,%5,%6,%7}, {%8,%9}, {%0,%1,%2,%3};" \
                 : "+f"((c)[0]), "+f"((c)[1]), "+f"((c)[2]), "+f"((c)[3]) \
                 : "r"((a)[0]), "r"((a)[1]), "r"((a)[2]), "r"((a)[3]), \
                   "r"((b)[0]), "r"((b)[1]))
#define MMA16816H(c, a, b) \
    asm volatile("mma.sync.aligned.m16n8k16.row.col.f32.f16.f16.f32 " \
                 "{%0,%1,%2,%3}, {%4,%5,%6,%7}, {%8,%9}, {%0,%1,%2,%3};" \
                 : "+f"((c)[0]), "+f"((c)[1]), "+f"((c)[2]), "+f"((c)[3]) \
                 : "r"((a)[0]), "r"((a)[1]), "r"((a)[2]), "r"((a)[3]), \
                   "r"((b)[0]), "r"((b)[1]))
#define CPA16(saddr, gptr) \
    asm volatile("cp.async.cg.shared.global [%0], [%1], 16;" :: "r"(saddr), "l"(gptr))
#define CPA_COMMIT() asm volatile("cp.async.commit_group;")
#define CPA_WAIT(N)  asm volatile("cp.async.wait_group %0;" :: "n"(N))

// ---------------- weight prep ----------------------------------------------
__global__ void split_w(const float* __restrict__ Wq, const float* __restrict__ Wk,
                        const float* __restrict__ Wv, const float* __restrict__ Wo) {
    int i = blockIdx.x * 256 + threadIdx.x;
    if (i < MQKV * CIN) {
        float v = (i < CQK * CIN) ? Wq[i]
                : (i < 2 * CQK * CIN) ? Wk[i - CQK * CIN]
                : Wv[i - 2 * CQK * CIN];
        g_wf[i] = __float2half(v);
    } else {
        int j = i - MQKV * CIN;
        if (j < CIN * CV) {
            float v = Wo[j];
            bf16 h = __float2bfloat16(v);
            g_woh[j] = h;
            g_wol[j] = __float2bfloat16(v - __bfloat162float(h));
        }
    }
}

// ---------------- transpose -> single fp16: src[R,HW] -> dst[HW,R] ----------
__global__ __launch_bounds__(256)
void trsp_h(const float* __restrict__ src, __half* __restrict__ dst,
            int R, size_t sStride, size_t dStride) {
    __shared__ float t[32][33];
    int n = blockIdx.z;
    src += (size_t)n * sStride;
    dst += (size_t)n * dStride;
    int c0 = blockIdx.x * 32, r0 = blockIdx.y * 32;
    int tx = threadIdx.x, ty = threadIdx.y;
    #pragma unroll
    for (int it = 0; it < 4; it++)
        t[ty + 8 * it][tx] = src[(size_t)(r0 + ty + 8 * it) * HW + c0 + tx];
    __syncthreads();
    #pragma unroll
    for (int it = 0; it < 4; it++)
        dst[(size_t)(c0 + ty + 8 * it) * R + r0 + tx] = __float2half(t[tx][ty + 8 * it]);
}

// ---------------- QKV projection: single fp16 product -----------------------
// grid (HW/128, MQKV/64, NB); 8 warps (2m x 4n), warp 32x32.
__global__ __launch_bounds__(256, 2)
void qkv_hmma() {
    __shared__ __align__(16) __half sA[64 * 32];
    __shared__ __align__(16) __half sB[128 * 32];
    int tid = threadIdx.x, lane = tid & 31, wid = tid >> 5;
    int wm = wid & 1, wn = wid >> 1;
    int n = blockIdx.z, m0 = blockIdx.y * 64, l0 = blockIdx.x * 128;

    const __half* xtf = g_xtf + (size_t)n * HW * CIN;
    uint32_t sa = smem_u32(sA), sb = smem_u32(sB);

    float acc[2][4][4] = {};

    for (int ck = 0; ck < CIN / 32; ck++) {
        {
            int row = tid >> 2, ch = tid & 3;
            uint32_t sw = SW64(row * 64 + ch * 16);
            *(float4*)((char*)sA + sw) =
                *(const float4*)(const void*)(g_wf + (size_t)(m0 + row) * CIN + ck * 32 + ch * 8);
        }
        #pragma unroll
        for (int t = 0; t < 2; t++) {
            int idx = tid + t * 256;
            int row = idx >> 2, ch = idx & 3;
            uint32_t sw = SW64(row * 64 + ch * 16);
            *(float4*)((char*)sB + sw) =
                *(const float4*)(const void*)(xtf + (size_t)(l0 + row) * CIN + ck * 32 + ch * 8);
        }
        __syncthreads();

        #pragma unroll
        for (int ks = 0; ks < 2; ks++) {
            uint32_t a[2][4], b[4][2];
            #pragma unroll
            for (int mt = 0; mt < 2; mt++) {
                int r = wm * 32 + mt * 16 + (lane & 15);
                uint32_t sw = SW64(r * 64 + ks * 32 + (lane >> 4) * 16);
                LDSM4(a[mt][0], a[mt][1], a[mt][2], a[mt][3], sa + sw);
            }
            #pragma unroll
            for (int nt = 0; nt < 4; nt++) {
                int r = wn * 32 + nt * 8 + (lane & 7);
                uint32_t sw = SW64(r * 64 + ks * 32 + ((lane >> 3) & 1) * 16);
                LDSM2(b[nt][0], b[nt][1], sb + sw);
            }
            #pragma unroll
            for (int mt = 0; mt < 2; mt++)
                #pragma unroll
                for (int nt = 0; nt < 4; nt++)
                    MMA16816H(acc[mt][nt], a[mt], b[nt]);
        }
        __syncthreads();
    }

    #pragma unroll
    for (int mt = 0; mt < 2; mt++) {
        int m = m0 + wm * 32 + mt * 16 + (lane >> 2);
        float* r0p = g_qkv + ((size_t)n * MQKV + m) * HW + l0 + wn * 32 + (lane & 3) * 2;
        float* r1p = r0p + 8 * HW;
        #pragma unroll
        for (int nt = 0; nt < 4; nt++) {
            *(float2*)(r0p + nt * 8) = make_float2(acc[mt][nt][0], acc[mt][nt][1]);
            *(float2*)(r1p + nt * 8) = make_float2(acc[mt][nt][2], acc[mt][nt][3]);
        }
    }
}

// ---------------- Et + exp fused: single fp16 product -----------------------
__global__ __launch_bounds__(256, 2)
void et_exp_hmma() {
    __shared__ __align__(16) __half sA[128 * 32];
    __shared__ __align__(16) __half sB[128 * 32];
    int tid = threadIdx.x, lane = tid & 31, wid = tid >> 5;
    int wm = wid & 1, wn = wid >> 1;
    int n = blockIdx.z, i0 = blockIdx.x * 128, j0 = blockIdx.y * 128;

    const __half* t64 = g_qkT + (size_t)n * HW * 64;
    uint32_t sa = smem_u32(sA), sb = smem_u32(sB);

    #pragma unroll
    for (int t = 0; t < 2; t++) {
        int idx = tid + t * 256;
        int row = idx >> 2, ch = idx & 3;
        uint32_t sw = SW64(row * 64 + ch * 16);
        *(float4*)((char*)sA + sw) = *(const float4*)(const void*)(t64 + (size_t)(j0 + row) * 64 + 32 + ch * 8);
        *(float4*)((char*)sB + sw) = *(const float4*)(const void*)(t64 + (size_t)(i0 + row) * 64 + ch * 8);
    }
    __syncthreads();

    float acc[4][4][4] = {};
    #pragma unroll
    for (int ks = 0; ks < 2; ks++) {
        uint32_t a[4][4], b[4][2];
        #pragma unroll
        for (int mt = 0; mt < 4; mt++) {
            int r = wm * 64 + mt * 16 + (lane & 15);
            uint32_t sw = SW64(r * 64 + ks * 32 + (lane >> 4) * 16);
            LDSM4(a[mt][0], a[mt][1], a[mt][2], a[mt][3], sa + sw);
        }
        #pragma unroll
        for (int nt = 0; nt < 4; nt++) {
            int r = wn * 32 + nt * 8 + (lane & 7);
            uint32_t sw = SW64(r * 64 + ks * 32 + ((lane >> 3) & 1) * 16);
            LDSM2(b[nt][0], b[nt][1], sb + sw);
        }
        #pragma unroll
        for (int mt = 0; mt < 4; mt++)
            #pragma unroll
            for (int nt = 0; nt < 4; nt++)
                MMA16816H(acc[mt][nt], a[mt], b[nt]);
    }

    __half* pf = g_pf + (size_t)n * HW * HW;
    float cs[4][2];
    #pragma unroll
    for (int nt = 0; nt < 4; nt++) { cs[nt][0] = 0.0f; cs[nt][1] = 0.0f; }

    #pragma unroll
    for (int mt = 0; mt < 4; mt++) {
        int j = j0 + wm * 64 + mt * 16 + (lane >> 2);
        #pragma unroll
        for (int nt = 0; nt < 4; nt++) {
            int ib = i0 + wn * 32 + nt * 8 + (lane & 3) * 2;
            float p0 = __expf(acc[mt][nt][0]);
            float p1 = __expf(acc[mt][nt][1]);
            float p2 = __expf(acc[mt][nt][2]);
            float p3 = __expf(acc[mt][nt][3]);
            *(__half2*)(pf + (size_t)j * HW + ib) = __floats2half2_rn(p0, p1);
            *(__half2*)(pf + (size_t)(j + 8) * HW + ib) = __floats2half2_rn(p2, p3);
            cs[nt][0] += p0 + p2;
            cs[nt][1] += p1 + p3;
        }
    }
    int seg = blockIdx.y * 2 + wm;
    #pragma unroll
    for (int nt = 0; nt < 4; nt++) {
        #pragma unroll
        for (int c = 0; c < 2; c++) {
            float s = cs[nt][c];
            s += __shfl_xor_sync(0xFFFFFFFFu, s, 4);
            s += __shfl_xor_sync(0xFFFFFFFFu, s, 8);
            s += __shfl_xor_sync(0xFFFFFFFFu, s, 16);
            if ((lane >> 2) == 0) {
                int i = i0 + wn * 32 + nt * 8 + (lane & 3) * 2 + c;
                g_sp[((size_t)n * SSEG + seg) * HW + i] = s;
            }
        }
    }
}

// ---------------- finalize col sums, V'' = V / s * VSCALE (fp16) ------------
__global__ __launch_bounds__(256)
void sum_fin() {
    size_t t = (size_t)blockIdx.x * 256 + threadIdx.x;
    size_t n = t / HW, i = t % HW;
    float s = 0.0f;
    #pragma unroll
    for (int sg = 0; sg < SSEG; sg++)
        s += g_sp[(n * SSEG + sg) * HW + i];
    g_s[t] = s;
}
__global__ __launch_bounds__(256)
void conv_v() {
    size_t idx = (size_t)blockIdx.x * 256 + threadIdx.x;
    size_t n = idx / ((size_t)CV * HW);
    size_t rem = idx % ((size_t)CV * HW);
    size_t r = rem / HW, i = rem % HW;
    float v = g_qkv[((size_t)n * MQKV + 2 * CQK + r) * HW + i];
    g_vf[idx] = __float2half(v / g_s[n * HW + i] * VSCALE);
}

// ---------------- O^T = P @ V''^T  fp16, cp.async pipelined -----------------
#define NCK (HW / 64)
__global__ __launch_bounds__(256, 2)
void mma_ot() {
    __shared__ __align__(16) __half sA[2][128 * 64];
    __shared__ __align__(16) __half sB[2][128 * 64];
    int tid = threadIdx.x, lane = tid & 31, wid = tid >> 5;
    int wm = wid & 1, wn = wid >> 1;
    int n = blockIdx.z, v0 = blockIdx.x * 128, j0 = blockIdx.y * 128;

    const __half* A = g_pf + (size_t)n * HW * HW + (size_t)j0 * HW;
    const __half* B = g_vf + ((size_t)n * CV + v0) * HW;
    uint32_t sa[2] = { smem_u32(sA[0]), smem_u32(sA[1]) };
    uint32_t sb[2] = { smem_u32(sB[0]), smem_u32(sB[1]) };

    auto issue = [&](int ck, int buf) {
        #pragma unroll
        for (int t = 0; t < 4; t++) {
            int idx = tid + t * 256;
            int row = idx >> 3, c = idx & 7;
            uint32_t sw = SW128(row * 128 + c * 16);
            size_t go = (size_t)row * HW + (size_t)ck * 64 + c * 8;
            CPA16(sa[buf] + sw, A + go);
            CPA16(sb[buf] + sw, B + go);
        }
    };

    float acc[4][4][4] = {};

    issue(0, 0);
    CPA_COMMIT();
    for (int ck = 0; ck < NCK; ck++) {
        int buf = ck & 1;
        if (ck + 1 < NCK) {
            issue(ck + 1, buf ^ 1);
            CPA_COMMIT();
            CPA_WAIT(1);
        } else {
            CPA_WAIT(0);
        }
        __syncthreads();

        #pragma unroll
        for (int ks = 0; ks < 4; ks++) {
            uint32_t a[4][4], b[4][2];
            #pragma unroll
            for (int mt = 0; mt < 4; mt++) {
                int r = wm * 64 + mt * 16 + (lane & 15);
                uint32_t sw = SW128(r * 128 + ks * 32 + (lane >> 4) * 16);
                LDSM4(a[mt][0], a[mt][1], a[mt][2], a[mt][3], sa[buf] + sw);
            }
            #pragma unroll
            for (int nt = 0; nt < 4; nt++) {
                int r = wn * 32 + nt * 8 + (lane & 7);
                uint32_t sw = SW128(r * 128 + ks * 32 + ((lane >> 3) & 1) * 16);
                LDSM2(b[nt][0], b[nt][1], sb[buf] + sw);
            }
            #pragma unroll
            for (int mt = 0; mt < 4; mt++)
                #pragma unroll
                for (int nt = 0; nt < 4; nt++)
                    MMA16816H(acc[mt][nt], a[mt], b[nt]);
        }
        __syncthreads();
    }

    bf16* oth = g_oth + (size_t)n * HW * CV;
    bf16* otl = g_otl + (size_t)n * HW * CV;
    #pragma unroll
    for (int mt = 0; mt < 4; mt++) {
        int j = j0 + wm * 64 + mt * 16 + (lane >> 2);
        int vb = v0 + wn * 32 + (lane & 3) * 2;
        #pragma unroll
        for (int nt = 0; nt < 4; nt++) {
            float p0 = acc[mt][nt][0], p1 = acc[mt][nt][1];
            float p2 = acc[mt][nt][2], p3 = acc[mt][nt][3];
            bf16 h0 = __float2bfloat16(p0), h1 = __float2bfloat16(p1);
            bf16 h2 = __float2bfloat16(p2), h3 = __float2bfloat16(p3);
            __nv_bfloat162 hv0; hv0.x = h0; hv0.y = h1;
            __nv_bfloat162 hv1; hv1.x = h2; hv1.y = h3;
            __nv_bfloat162 lv0; lv0.x = __float2bfloat16(p0 - __bfloat162float(h0));
                                lv0.y = __float2bfloat16(p1 - __bfloat162float(h1));
            __nv_bfloat162 lv1; lv1.x = __float2bfloat16(p2 - __bfloat162float(h2));
                                lv1.y = __float2bfloat16(p3 - __bfloat162float(h3));
            *(__nv_bfloat162*)(oth + (size_t)j * CV + vb + nt * 8) = hv0;
            *(__nv_bfloat162*)(oth + (size_t)(j + 8) * CV + vb + nt * 8) = hv1;
            *(__nv_bfloat162*)(otl + (size_t)j * CV + vb + nt * 8) = lv0;
            *(__nv_bfloat162*)(otl + (size_t)(j + 8) * CV + vb + nt * 8) = lv1;
        }
    }
}

// ---------------- out = (gamma/VSCALE) * Wo @ O, cp.async pipelined ----------
#define WCK (CV / 32)
__global__ __launch_bounds__(256, 2)
void wo_hmma(float* __restrict__ out, const float* __restrict__ gammaPtr) {
    __shared__ __align__(16) bf16 sAh[2][128 * 32], sAl[2][128 * 32];
    __shared__ __align__(16) bf16 sBh[2][128 * 32], sBl[2][128 * 32];
    int tid = threadIdx.x, lane = tid & 31, wid = tid >> 5;
    int wm = wid & 1, wn = wid >> 1;
    int n = blockIdx.z, o0 = blockIdx.y * 128, l0 = blockIdx.x * 128;

    const bf16* oth = g_oth + (size_t)n * HW * CV;
    const bf16* otl = g_otl + (size_t)n * HW * CV;
    uint32_t sa_h[2] = { smem_u32(sAh[0]), smem_u32(sAh[1]) };
    uint32_t sa_l[2] = { smem_u32(sAl[0]), smem_u32(sAl[1]) };
    uint32_t sb_h[2] = { smem_u32(sBh[0]), smem_u32(sBh[1]) };
    uint32_t sb_l[2] = { smem_u32(sBl[0]), smem_u32(sBl[1]) };

    auto issue = [&](int ck, int buf) {
        #pragma unroll
        for (int t = 0; t < 2; t++) {
            int idx = tid + t * 256;
            int row = idx >> 2, ch = idx & 3;
            uint32_t sw = SW64(row * 64 + ch * 16);
            size_t ga = (size_t)(o0 + row) * CV + ck * 32 + ch * 8;
            size_t gb = (size_t)(l0 + row) * CV + ck * 32 + ch * 8;
            CPA16(sa_h[buf] + sw, g_woh + ga);
            CPA16(sa_l[buf] + sw, g_wol + ga);
            CPA16(sb_h[buf] + sw, oth + gb);
            CPA16(sb_l[buf] + sw, otl + gb);
        }
    };

    float acc[4][4][4] = {};

    issue(0, 0);
    CPA_COMMIT();
    for (int ck = 0; ck < WCK; ck++) {
        int buf = ck & 1;
        if (ck + 1 < WCK) {
            issue(ck + 1, buf ^ 1);
            CPA_COMMIT();
            CPA_WAIT(1);
        } else {
            CPA_WAIT(0);
        }
        __syncthreads();

        #pragma unroll
        for (int ks = 0; ks < 2; ks++) {
            uint32_t a[4][4], bh[4][2], bl[4][2];
            uint32_t a_off[4];
            #pragma unroll
            for (int mt = 0; mt < 4; mt++) {
                int r = wm * 64 + mt * 16 + (lane & 15);
                a_off[mt] = SW64(r * 64 + ks * 32 + (lane >> 4) * 16);
                LDSM4(a[mt][0], a[mt][1], a[mt][2], a[mt][3], sa_h[buf] + a_off[mt]);
            }
            #pragma unroll
            for (int nt = 0; nt < 4; nt++) {
                int r = wn * 32 + nt * 8 + (lane & 7);
                uint32_t sw = SW64(r * 64 + ks * 32 + ((lane >> 3) & 1) * 16);
                LDSM2(bh[nt][0], bh[nt][1], sb_h[buf] + sw);
                LDSM2(bl[nt][0], bl[nt][1], sb_l[buf] + sw);
            }
            #pragma unroll
            for (int mt = 0; mt < 4; mt++)
                #pragma unroll
                for (int nt = 0; nt < 4; nt++) {
                    MMA16816(acc[mt][nt], a[mt], bh[nt]);
                    MMA16816(acc[mt][nt], a[mt], bl[nt]);
                }
            #pragma unroll
            for (int mt = 0; mt < 4; mt++)
                LDSM4(a[mt][0], a[mt][1], a[mt][2], a[mt][3], sa_l[buf] + a_off[mt]);
            #pragma unroll
            for (int mt = 0; mt < 4; mt++)
                #pragma unroll
                for (int nt = 0; nt < 4; nt++)
                    MMA16816(acc[mt][nt], a[mt], bh[nt]);
        }
        __syncthreads();
    }

    float gamma = *gammaPtr * (1.0f / VSCALE);
    #pragma unroll
    for (int mt = 0; mt < 4; mt++) {
        int o = o0 + wm * 64 + mt * 16 + (lane >> 2);
        float* r0p = out + ((size_t)n * CIN + o) * HW + l0 + wn * 32 + (lane & 3) * 2;
        float* r1p = r0p + 8 * HW;
        #pragma unroll
        for (int nt = 0; nt < 4; nt++) {
            *(float2*)(r0p + nt * 8) = make_float2(gamma * acc[mt][nt][0], gamma * acc[mt][nt][1]);
            *(float2*)(r1p + nt * 8) = make_float2(gamma * acc[mt][nt][2], gamma * acc[mt][nt][3]);
        }
    }
}

// ---------------- launch ----------------------------------------------------
extern "C" void kernel_launch(void* const* d_in, const int* in_sizes, int n_in,
                              void* d_out, int out_size) {
    const float* x     = (const float*)d_in[0];
    const float* Wq    = (const float*)d_in[1];
    const float* Wk    = (const float*)d_in[2];
    const float* Wv    = (const float*)d_in[3];
    const float* Wo    = (const float*)d_in[4];
    const float* gamma = (const float*)d_in[5];
    float* out = (float*)d_out;

    float* qkv = nullptr;  cudaGetSymbolAddress((void**)&qkv, g_qkv);
    __half* xtf = nullptr; cudaGetSymbolAddress((void**)&xtf, g_xtf);
    __half* qkT = nullptr; cudaGetSymbolAddress((void**)&qkT, g_qkT);

    // 1. weights: qkv fp16, Wo bf16 split
    split_w<<<(MQKV * CIN + CIN * CV + 255) / 256, 256>>>(Wq, Wk, Wv, Wo);
    // 2. xT -> fp16
    trsp_h<<<dim3(HW / 32, CIN / 32, NB), dim3(32, 8)>>>(
        x, xtf, CIN, (size_t)CIN * HW, (size_t)HW * CIN);
    // 3. QKV projection (fp16 single product)
    qkv_hmma<<<dim3(HW / 128, MQKV / 64, NB), 256>>>();
    // 4. qT/kT -> fp16
    trsp_h<<<dim3(HW / 32, 2, NB), dim3(32, 8)>>>(
        qkv, qkT, 64, (size_t)MQKV * HW, (size_t)HW * 64);
    // 5. Et + exp fused -> P fp16, partial col sums
    et_exp_hmma<<<dim3(HW / 128, HW / 128, NB), 256>>>();
    // 6. finalize sums; V'' fp16
    sum_fin<<<(NB * HW) / 256, 256>>>();
    conv_v<<<(NB * CV * HW) / 256, 256>>>();
    // 7. O^T = P @ V''^T (fp16, pipelined)
    mma_ot<<<dim3(CV / 128, HW / 128, NB), 256>>>();
    // 8. out = (gamma/VSCALE) * Wo @ O (bf16 3-product, pipelined)
    wo_hmma<<<dim3(HW / 128, CIN / 128, NB), 256>>>(out, gamma);
}

// round 15
// speedup vs baseline: 2.5374x; 1.0406x over previous
#include <cuda_runtime.h>
#include <cuda_bf16.h>
#include <cuda_fp16.h>
#include <cstdint>
#include <cstddef>

#define HW   4096
#define CIN  256
#define CQK  32
#define CV   256
#define NB   8
#define MQKV 320
#define SSEG 64
#define VSCALE 1024.0f
#define SPITCH 136   // smem staging row pitch in halves (272B, 16B-aligned)

typedef __nv_bfloat16 bf16;

// ---------------- scratch -----------------------------------------------
__device__ __half g_wf[MQKV * CIN];                   // qkv weights fp16
__device__ bf16  g_woh[CIN * CV];
__device__ bf16  g_wol[CIN * CV];
__device__ __half g_xtf[(size_t)NB * HW * CIN];       // x^T fp16 [l, c]
__device__ float g_qk[(size_t)NB * 64 * HW];          // q,k rows fp32 [m<64, l]
__device__ __half g_vraw[(size_t)NB * CV * HW];       // V rows fp16 [v, l]
__device__ __half g_qkT[(size_t)NB * HW * 64];        // fp16 [l][0:32]=qT,[32:64]=kT
__device__ float g_sp[(size_t)NB * SSEG * HW];
__device__ float g_s[(size_t)NB * HW];
__device__ __half g_pf[(size_t)NB * HW * HW];         // P=exp(E) fp16 [j,i]
__device__ __half g_vf[(size_t)NB * CV * HW];         // (V/s)*1024 fp16 [v,i]
__device__ bf16  g_oth[(size_t)NB * HW * CV];         // O^T hi [l, v]
__device__ bf16  g_otl[(size_t)NB * HW * CV];

// ---------------- helpers -------------------------------------------------
static __device__ __forceinline__ uint32_t smem_u32(const void* p) {
    uint32_t a;
    asm("{ .reg .u64 t; cvta.to.shared.u64 t, %1; cvt.u32.u64 %0, t; }" : "=r"(a) : "l"(p));
    return a;
}
#define SW64(x)  ((x) ^ (((x) >> 3) & 0x30))
#define SW128(x) ((x) ^ (((x) >> 3) & 0x70))
#define LDSM4(r0, r1, r2, r3, addr) \
    asm volatile("ldmatrix.sync.aligned.m8n8.x4.shared.b16 {%0,%1,%2,%3}, [%4];" \
                 : "=r"(r0), "=r"(r1), "=r"(r2), "=r"(r3) : "r"(addr))
#define LDSM2(r0, r1, addr) \
    asm volatile("ldmatrix.sync.aligned.m8n8.x2.shared.b16 {%0,%1}, [%2];" \
                 : "=r"(r0), "=r"(r1) : "r"(addr))
#define MMA16816(c, a, b) \
    asm volatile("mma.sync.aligned.m16n8k16.row.col.f32.bf16.bf16.f32 " \
                 "{%0,%1,%2,%3}, {%4,%5,%6,%7}, {%8,%9}, {%0,%1,%2,%3};" \
                 : "+f"((c)[0]), "+f"((c)[1]), "+f"((c)[2]), "+f"((c)[3]) \
                 : "r"((a)[0]), "r"((a)[1]), "r"((a)[2]), "r"((a)[3]), \
                   "r"((b)[0]), "r"((b)[1]))
#define MMA16816H(c, a, b) \
    asm volatile("mma.sync.aligned.m16n8k16.row.col.f32.f16.f16.f32 " \
                 "{%0,%1,%2,%3}, {%4,%5,%6,%7}, {%8,%9}, {%0,%1,%2,%3};" \
                 : "+f"((c)[0]), "+f"((c)[1]), "+f"((c)[2]), "+f"((c)[3]) \
                 : "r"((a)[0]), "r"((a)[1]), "r"((a)[2]), "r"((a)[3]), \
                   "r"((b)[0]), "r"((b)[1]))
#define CPA16(saddr, gptr) \
    asm volatile("cp.async.cg.shared.global [%0], [%1], 16;" :: "r"(saddr), "l"(gptr))
#define CPA_COMMIT() asm volatile("cp.async.commit_group;")
#define CPA_WAIT(N)  asm volatile("cp.async.wait_group %0;" :: "n"(N))

// ---------------- weight prep ----------------------------------------------
__global__ void split_w(const float* __restrict__ Wq, const float* __restrict__ Wk,
                        const float* __restrict__ Wv, const float* __restrict__ Wo) {
    int i = blockIdx.x * 256 + threadIdx.x;
    if (i < MQKV * CIN) {
        float v = (i < CQK * CIN) ? Wq[i]
                : (i < 2 * CQK * CIN) ? Wk[i - CQK * CIN]
                : Wv[i - 2 * CQK * CIN];
        g_wf[i] = __float2half(v);
    } else {
        int j = i - MQKV * CIN;
        if (j < CIN * CV) {
            float v = Wo[j];
            bf16 h = __float2bfloat16(v);
            g_woh[j] = h;
            g_wol[j] = __float2bfloat16(v - __bfloat162float(h));
        }
    }
}

// ---------------- transpose -> single fp16: src[R,HW] -> dst[HW,R] ----------
__global__ __launch_bounds__(256)
void trsp_h(const float* __restrict__ src, __half* __restrict__ dst,
            int R, size_t sStride, size_t dStride) {
    __shared__ float t[32][33];
    int n = blockIdx.z;
    src += (size_t)n * sStride;
    dst += (size_t)n * dStride;
    int c0 = blockIdx.x * 32, r0 = blockIdx.y * 32;
    int tx = threadIdx.x, ty = threadIdx.y;
    #pragma unroll
    for (int it = 0; it < 4; it++)
        t[ty + 8 * it][tx] = src[(size_t)(r0 + ty + 8 * it) * HW + c0 + tx];
    __syncthreads();
    #pragma unroll
    for (int it = 0; it < 4; it++)
        dst[(size_t)(c0 + ty + 8 * it) * R + r0 + tx] = __float2half(t[tx][ty + 8 * it]);
}

// ---------------- QKV projection: single fp16 product -----------------------
// grid (HW/128, MQKV/64, NB). y==0 -> q/k rows fp32; y>=1 -> V rows fp16.
__global__ __launch_bounds__(256, 2)
void qkv_hmma() {
    __shared__ __align__(16) __half sA[64 * 32];
    __shared__ __align__(16) __half sB[128 * 32];
    int tid = threadIdx.x, lane = tid & 31, wid = tid >> 5;
    int wm = wid & 1, wn = wid >> 1;
    int n = blockIdx.z, m0 = blockIdx.y * 64, l0 = blockIdx.x * 128;

    const __half* xtf = g_xtf + (size_t)n * HW * CIN;
    uint32_t sa = smem_u32(sA), sb = smem_u32(sB);

    float acc[2][4][4] = {};

    for (int ck = 0; ck < CIN / 32; ck++) {
        {
            int row = tid >> 2, ch = tid & 3;
            uint32_t sw = SW64(row * 64 + ch * 16);
            *(float4*)((char*)sA + sw) =
                *(const float4*)(const void*)(g_wf + (size_t)(m0 + row) * CIN + ck * 32 + ch * 8);
        }
        #pragma unroll
        for (int t = 0; t < 2; t++) {
            int idx = tid + t * 256;
            int row = idx >> 2, ch = idx & 3;
            uint32_t sw = SW64(row * 64 + ch * 16);
            *(float4*)((char*)sB + sw) =
                *(const float4*)(const void*)(xtf + (size_t)(l0 + row) * CIN + ck * 32 + ch * 8);
        }
        __syncthreads();

        #pragma unroll
        for (int ks = 0; ks < 2; ks++) {
            uint32_t a[2][4], b[4][2];
            #pragma unroll
            for (int mt = 0; mt < 2; mt++) {
                int r = wm * 32 + mt * 16 + (lane & 15);
                uint32_t sw = SW64(r * 64 + ks * 32 + (lane >> 4) * 16);
                LDSM4(a[mt][0], a[mt][1], a[mt][2], a[mt][3], sa + sw);
            }
            #pragma unroll
            for (int nt = 0; nt < 4; nt++) {
                int r = wn * 32 + nt * 8 + (lane & 7);
                uint32_t sw = SW64(r * 64 + ks * 32 + ((lane >> 3) & 1) * 16);
                LDSM2(b[nt][0], b[nt][1], sb + sw);
            }
            #pragma unroll
            for (int mt = 0; mt < 2; mt++)
                #pragma unroll
                for (int nt = 0; nt < 4; nt++)
                    MMA16816H(acc[mt][nt], a[mt], b[nt]);
        }
        __syncthreads();
    }

    if (m0 == 0) {
        #pragma unroll
        for (int mt = 0; mt < 2; mt++) {
            int m = wm * 32 + mt * 16 + (lane >> 2);
            float* r0p = g_qk + ((size_t)n * 64 + m) * HW + l0 + wn * 32 + (lane & 3) * 2;
            float* r1p = r0p + 8 * HW;
            #pragma unroll
            for (int nt = 0; nt < 4; nt++) {
                *(float2*)(r0p + nt * 8) = make_float2(acc[mt][nt][0], acc[mt][nt][1]);
                *(float2*)(r1p + nt * 8) = make_float2(acc[mt][nt][2], acc[mt][nt][3]);
            }
        }
    } else {
        __half* vb = g_vraw + (size_t)n * CV * HW;
        #pragma unroll
        for (int mt = 0; mt < 2; mt++) {
            int v = m0 - 64 + wm * 32 + mt * 16 + (lane >> 2);
            __half* r0p = vb + (size_t)v * HW + l0 + wn * 32 + (lane & 3) * 2;
            __half* r1p = r0p + 8 * HW;
            #pragma unroll
            for (int nt = 0; nt < 4; nt++) {
                *(__half2*)(r0p + nt * 8) = __floats2half2_rn(acc[mt][nt][0], acc[mt][nt][1]);
                *(__half2*)(r1p + nt * 8) = __floats2half2_rn(acc[mt][nt][2], acc[mt][nt][3]);
            }
        }
    }
}

// ---------------- Et + exp fused, SMEM-staged coalesced P writes ------------
__global__ __launch_bounds__(256, 2)
void et_exp_hmma() {
    // phase 1: [0:8K) = A (kT), [8K:16K) = B (qT). phase 2: whole = P staging.
    __shared__ __align__(16) char sm[128 * SPITCH * 2];  // 34816 B
    __half* sA = (__half*)sm;
    __half* sB = (__half*)(sm + 8192);
    __half* sP = (__half*)sm;

    int tid = threadIdx.x, lane = tid & 31, wid = tid >> 5;
    int wm = wid & 1, wn = wid >> 1;
    int n = blockIdx.z, i0 = blockIdx.x * 128, j0 = blockIdx.y * 128;

    const __half* t64 = g_qkT + (size_t)n * HW * 64;
    uint32_t sa = smem_u32(sA), sb = smem_u32(sB);

    #pragma unroll
    for (int t = 0; t < 2; t++) {
        int idx = tid + t * 256;
        int row = idx >> 2, ch = idx & 3;
        uint32_t sw = SW64(row * 64 + ch * 16);
        *(float4*)((char*)sA + sw) = *(const float4*)(const void*)(t64 + (size_t)(j0 + row) * 64 + 32 + ch * 8);
        *(float4*)((char*)sB + sw) = *(const float4*)(const void*)(t64 + (size_t)(i0 + row) * 64 + ch * 8);
    }
    __syncthreads();

    float acc[4][4][4] = {};
    #pragma unroll
    for (int ks = 0; ks < 2; ks++) {
        uint32_t a[4][4], b[4][2];
        #pragma unroll
        for (int mt = 0; mt < 4; mt++) {
            int r = wm * 64 + mt * 16 + (lane & 15);
            uint32_t sw = SW64(r * 64 + ks * 32 + (lane >> 4) * 16);
            LDSM4(a[mt][0], a[mt][1], a[mt][2], a[mt][3], sa + sw);
        }
        #pragma unroll
        for (int nt = 0; nt < 4; nt++) {
            int r = wn * 32 + nt * 8 + (lane & 7);
            uint32_t sw = SW64(r * 64 + ks * 32 + ((lane >> 3) & 1) * 16);
            LDSM2(b[nt][0], b[nt][1], sb + sw);
        }
        #pragma unroll
        for (int mt = 0; mt < 4; mt++)
            #pragma unroll
            for (int nt = 0; nt < 4; nt++)
                MMA16816H(acc[mt][nt], a[mt], b[nt]);
    }
    __syncthreads();   // A/B dead; reuse as P staging

    float cs[4][2];
    #pragma unroll
    for (int nt = 0; nt < 4; nt++) { cs[nt][0] = 0.0f; cs[nt][1] = 0.0f; }

    #pragma unroll
    for (int mt = 0; mt < 4; mt++) {
        int jl = wm * 64 + mt * 16 + (lane >> 2);
        #pragma unroll
        for (int nt = 0; nt < 4; nt++) {
            int il = wn * 32 + nt * 8 + (lane & 3) * 2;
            float p0 = __expf(acc[mt][nt][0]);
            float p1 = __expf(acc[mt][nt][1]);
            float p2 = __expf(acc[mt][nt][2]);
            float p3 = __expf(acc[mt][nt][3]);
            *(__half2*)(sP + jl * SPITCH + il) = __floats2half2_rn(p0, p1);
            *(__half2*)(sP + (jl + 8) * SPITCH + il) = __floats2half2_rn(p2, p3);
            cs[nt][0] += p0 + p2;
            cs[nt][1] += p1 + p3;
        }
    }
    int seg = blockIdx.y * 2 + wm;
    #pragma unroll
    for (int nt = 0; nt < 4; nt++) {
        #pragma unroll
        for (int c = 0; c < 2; c++) {
            float s = cs[nt][c];
            s += __shfl_xor_sync(0xFFFFFFFFu, s, 4);
            s += __shfl_xor_sync(0xFFFFFFFFu, s, 8);
            s += __shfl_xor_sync(0xFFFFFFFFu, s, 16);
            if ((lane >> 2) == 0) {
                int i = i0 + wn * 32 + nt * 8 + (lane & 3) * 2 + c;
                g_sp[((size_t)n * SSEG + seg) * HW + i] = s;
            }
        }
    }
    __syncthreads();

    // coalesced P writeout: 128 rows x 256B (16 segs of 16B)
    __half* pf = g_pf + (size_t)n * HW * HW;
    #pragma unroll
    for (int it = 0; it < 8; it++) {
        int idx = tid + it * 256;            // 0..2047
        int row = idx >> 4, sg = idx & 15;
        *(float4*)(pf + (size_t)(j0 + row) * HW + i0 + sg * 8) =
            *(const float4*)(sP + row * SPITCH + sg * 8);
    }
}

// ---------------- finalize col sums, V'' = V / s * VSCALE (fp16) ------------
__global__ __launch_bounds__(256)
void sum_fin() {
    size_t t = (size_t)blockIdx.x * 256 + threadIdx.x;
    size_t n = t / HW, i = t % HW;
    float s = 0.0f;
    #pragma unroll
    for (int sg = 0; sg < SSEG; sg++)
        s += g_sp[(n * SSEG + sg) * HW + i];
    g_s[t] = s;
}
__global__ __launch_bounds__(256)
void conv_v() {
    size_t idx = (size_t)blockIdx.x * 256 + threadIdx.x;
    size_t n = idx / ((size_t)CV * HW);
    size_t i = idx % HW;
    float v = __half2float(g_vraw[idx]);
    g_vf[idx] = __float2half(v / g_s[n * HW + i] * VSCALE);
}

// ---------------- O^T = P @ V''^T  fp16, cp.async pipelined -----------------
#define NCK (HW / 64)
__global__ __launch_bounds__(256, 2)
void mma_ot() {
    // one block: 4 x (128x64) fp16 buffers = 65536 B; epilogue staging needs
    // 128*SPITCH*2 = 34816 B <= 65536 B.
    __shared__ __align__(16) __half sMem[4 * 128 * 64];
    int tid = threadIdx.x, lane = tid & 31, wid = tid >> 5;
    int wm = wid & 1, wn = wid >> 1;
    int n = blockIdx.z, v0 = blockIdx.x * 128, j0 = blockIdx.y * 128;

    const __half* A = g_pf + (size_t)n * HW * HW + (size_t)j0 * HW;
    const __half* B = g_vf + ((size_t)n * CV + v0) * HW;
    uint32_t sa[2] = { smem_u32(sMem), smem_u32(sMem + 128 * 64) };
    uint32_t sb[2] = { smem_u32(sMem + 2 * 128 * 64), smem_u32(sMem + 3 * 128 * 64) };

    auto issue = [&](int ck, int buf) {
        #pragma unroll
        for (int t = 0; t < 4; t++) {
            int idx = tid + t * 256;
            int row = idx >> 3, c = idx & 7;
            uint32_t sw = SW128(row * 128 + c * 16);
            size_t go = (size_t)row * HW + (size_t)ck * 64 + c * 8;
            CPA16(sa[buf] + sw, A + go);
            CPA16(sb[buf] + sw, B + go);
        }
    };

    float acc[4][4][4] = {};

    issue(0, 0);
    CPA_COMMIT();
    for (int ck = 0; ck < NCK; ck++) {
        int buf = ck & 1;
        if (ck + 1 < NCK) {
            issue(ck + 1, buf ^ 1);
            CPA_COMMIT();
            CPA_WAIT(1);
        } else {
            CPA_WAIT(0);
        }
        __syncthreads();

        #pragma unroll
        for (int ks = 0; ks < 4; ks++) {
            uint32_t a[4][4], b[4][2];
            #pragma unroll
            for (int mt = 0; mt < 4; mt++) {
                int r = wm * 64 + mt * 16 + (lane & 15);
                uint32_t sw = SW128(r * 128 + ks * 32 + (lane >> 4) * 16);
                LDSM4(a[mt][0], a[mt][1], a[mt][2], a[mt][3], sa[buf] + sw);
            }
            #pragma unroll
            for (int nt = 0; nt < 4; nt++) {
                int r = wn * 32 + nt * 8 + (lane & 7);
                uint32_t sw = SW128(r * 128 + ks * 32 + ((lane >> 3) & 1) * 16);
                LDSM2(b[nt][0], b[nt][1], sb[buf] + sw);
            }
            #pragma unroll
            for (int mt = 0; mt < 4; mt++)
                #pragma unroll
                for (int nt = 0; nt < 4; nt++)
                    MMA16816H(acc[mt][nt], a[mt], b[nt]);
        }
        __syncthreads();
    }

    // staged, coalesced O^T hi/lo writes (128 bf16 per row = 256 B = 16 segs)
    __half* stage = sMem;
    bf16* oth = g_oth + (size_t)n * HW * CV;
    bf16* otl = g_otl + (size_t)n * HW * CV;

    #pragma unroll
    for (int pass = 0; pass < 2; pass++) {
        #pragma unroll
        for (int mt = 0; mt < 4; mt++) {
            int jl = wm * 64 + mt * 16 + (lane >> 2);
            int vc = wn * 32 + (lane & 3) * 2;
            #pragma unroll
            for (int nt = 0; nt < 4; nt++) {
                float p0 = acc[mt][nt][0], p1 = acc[mt][nt][1];
                float p2 = acc[mt][nt][2], p3 = acc[mt][nt][3];
                __nv_bfloat162 w0, w1;
                if (pass == 0) {
                    w0.x = __float2bfloat16(p0); w0.y = __float2bfloat16(p1);
                    w1.x = __float2bfloat16(p2); w1.y = __float2bfloat16(p3);
                } else {
                    w0.x = __float2bfloat16(p0 - __bfloat162float(__float2bfloat16(p0)));
                    w0.y = __float2bfloat16(p1 - __bfloat162float(__float2bfloat16(p1)));
                    w1.x = __float2bfloat16(p2 - __bfloat162float(__float2bfloat16(p2)));
                    w1.y = __float2bfloat16(p3 - __bfloat162float(__float2bfloat16(p3)));
                }
                *(__nv_bfloat162*)(stage + jl * SPITCH + vc + nt * 8) = w0;
                *(__nv_bfloat162*)(stage + (jl + 8) * SPITCH + vc + nt * 8) = w1;
            }
        }
        __syncthreads();
        bf16* dst = (pass == 0) ? oth : otl;
        #pragma unroll
        for (int it = 0; it < 8; it++) {
            int idx = tid + it * 256;        // 0..2047: 128 rows x 16 segs(16B)
            int row = idx >> 4, sg = idx & 15;
            *(float4*)(dst + (size_t)(j0 + row) * CV + v0 + sg * 8) =
                *(const float4*)(stage + row * SPITCH + sg * 8);
        }
        __syncthreads();
    }
}

// ---------------- out = (gamma/VSCALE) * Wo @ O, cp.async pipelined ----------
#define WCK (CV / 32)
__global__ __launch_bounds__(256, 2)
void wo_hmma(float* __restrict__ out, const float* __restrict__ gammaPtr) {
    __shared__ __align__(16) bf16 sAh[2][128 * 32], sAl[2][128 * 32];
    __shared__ __align__(16) bf16 sBh[2][128 * 32], sBl[2][128 * 32];
    int tid = threadIdx.x, lane = tid & 31, wid = tid >> 5;
    int wm = wid & 1, wn = wid >> 1;
    int n = blockIdx.z, o0 = blockIdx.y * 128, l0 = blockIdx.x * 128;

    const bf16* oth = g_oth + (size_t)n * HW * CV;
    const bf16* otl = g_otl + (size_t)n * HW * CV;
    uint32_t sa_h[2] = { smem_u32(sAh[0]), smem_u32(sAh[1]) };
    uint32_t sa_l[2] = { smem_u32(sAl[0]), smem_u32(sAl[1]) };
    uint32_t sb_h[2] = { smem_u32(sBh[0]), smem_u32(sBh[1]) };
    uint32_t sb_l[2] = { smem_u32(sBl[0]), smem_u32(sBl[1]) };

    auto issue = [&](int ck, int buf) {
        #pragma unroll
        for (int t = 0; t < 2; t++) {
            int idx = tid + t * 256;
            int row = idx >> 2, ch = idx & 3;
            uint32_t sw = SW64(row * 64 + ch * 16);
            size_t ga = (size_t)(o0 + row) * CV + ck * 32 + ch * 8;
            size_t gb = (size_t)(l0 + row) * CV + ck * 32 + ch * 8;
            CPA16(sa_h[buf] + sw, g_woh + ga);
            CPA16(sa_l[buf] + sw, g_wol + ga);
            CPA16(sb_h[buf] + sw, oth + gb);
            CPA16(sb_l[buf] + sw, otl + gb);
        }
    };

    float acc[4][4][4] = {};

    issue(0, 0);
    CPA_COMMIT();
    for (int ck = 0; ck < WCK; ck++) {
        int buf = ck & 1;
        if (ck + 1 < WCK) {
            issue(ck + 1, buf ^ 1);
            CPA_COMMIT();
            CPA_WAIT(1);
        } else {
            CPA_WAIT(0);
        }
        __syncthreads();

        #pragma unroll
        for (int ks = 0; ks < 2; ks++) {
            uint32_t a[4][4], bh[4][2], bl[4][2];
            uint32_t a_off[4];
            #pragma unroll
            for (int mt = 0; mt < 4; mt++) {
                int r = wm * 64 + mt * 16 + (lane & 15);
                a_off[mt] = SW64(r * 64 + ks * 32 + (lane >> 4) * 16);
                LDSM4(a[mt][0], a[mt][1], a[mt][2], a[mt][3], sa_h[buf] + a_off[mt]);
            }
            #pragma unroll
            for (int nt = 0; nt < 4; nt++) {
                int r = wn * 32 + nt * 8 + (lane & 7);
                uint32_t sw = SW64(r * 64 + ks * 32 + ((lane >> 3) & 1) * 16);
                LDSM2(bh[nt][0], bh[nt][1], sb_h[buf] + sw);
                LDSM2(bl[nt][0], bl[nt][1], sb_l[buf] + sw);
            }
            #pragma unroll
            for (int mt = 0; mt < 4; mt++)
                #pragma unroll
                for (int nt = 0; nt < 4; nt++) {
                    MMA16816(acc[mt][nt], a[mt], bh[nt]);
                    MMA16816(acc[mt][nt], a[mt], bl[nt]);
                }
            #pragma unroll
            for (int mt = 0; mt < 4; mt++)
                LDSM4(a[mt][0], a[mt][1], a[mt][2], a[mt][3], sa_l[buf] + a_off[mt]);
            #pragma unroll
            for (int mt = 0; mt < 4; mt++)
                #pragma unroll
                for (int nt = 0; nt < 4; nt++)
                    MMA16816(acc[mt][nt], a[mt], bh[nt]);
        }
        __syncthreads();
    }

    float gamma = *gammaPtr * (1.0f / VSCALE);
    #pragma unroll
    for (int mt = 0; mt < 4; mt++) {
        int o = o0 + wm * 64 + mt * 16 + (lane >> 2);
        float* r0p = out + ((size_t)n * CIN + o) * HW + l0 + wn * 32 + (lane & 3) * 2;
        float* r1p = r0p + 8 * HW;
        #pragma unroll
        for (int nt = 0; nt < 4; nt++) {
            *(float2*)(r0p + nt * 8) = make_float2(gamma * acc[mt][nt][0], gamma * acc[mt][nt][1]);
            *(float2*)(r1p + nt * 8) = make_float2(gamma * acc[mt][nt][2], gamma * acc[mt][nt][3]);
        }
    }
}

// ---------------- launch ----------------------------------------------------
extern "C" void kernel_launch(void* const* d_in, const int* in_sizes, int n_in,
                              void* d_out, int out_size) {
    const float* x     = (const float*)d_in[0];
    const float* Wq    = (const float*)d_in[1];
    const float* Wk    = (const float*)d_in[2];
    const float* Wv    = (const float*)d_in[3];
    const float* Wo    = (const float*)d_in[4];
    const float* gamma = (const float*)d_in[5];
    float* out = (float*)d_out;

    float* qk = nullptr;   cudaGetSymbolAddress((void**)&qk,  g_qk);
    __half* xtf = nullptr; cudaGetSymbolAddress((void**)&xtf, g_xtf);
    __half* qkT = nullptr; cudaGetSymbolAddress((void**)&qkT, g_qkT);

    // 1. weights: qkv fp16, Wo bf16 split
    split_w<<<(MQKV * CIN + CIN * CV + 255) / 256, 256>>>(Wq, Wk, Wv, Wo);
    // 2. xT -> fp16
    trsp_h<<<dim3(HW / 32, CIN / 32, NB), dim3(32, 8)>>>(
        x, xtf, CIN, (size_t)CIN * HW, (size_t)HW * CIN);
    // 3. QKV projection (q/k fp32; V fp16 direct)
    qkv_hmma<<<dim3(HW / 128, MQKV / 64, NB), 256>>>();
    // 4. qT/kT -> fp16
    trsp_h<<<dim3(HW / 32, 2, NB), dim3(32, 8)>>>(
        qk, qkT, 64, (size_t)64 * HW, (size_t)HW * 64);
    // 5. Et + exp fused -> P fp16 (coalesced), partial col sums
    et_exp_hmma<<<dim3(HW / 128, HW / 128, NB), 256>>>();
    // 6. finalize sums; V'' fp16
    sum_fin<<<(NB * HW) / 256, 256>>>();
    conv_v<<<(NB * CV * HW) / 256, 256>>>();
    // 7. O^T = P @ V''^T (fp16, pipelined, staged epilogue)
    mma_ot<<<dim3(CV / 128, HW / 128, NB), 256>>>();
    // 8. out = (gamma/VSCALE) * Wo @ O (bf16 3-product, pipelined)
    wo_hmma<<<dim3(HW / 128, CIN / 128, NB), 256>>>(out, gamma);
}

// round 16
// speedup vs baseline: 2.7148x; 1.0699x over previous
#include <cuda_runtime.h>
#include <cuda_bf16.h>
#include <cuda_fp16.h>
#include <cstdint>
#include <cstddef>

#define HW   4096
#define CIN  256
#define CQK  32
#define CV   256
#define NB   8
#define MQKV 320
#define SSEG 64
#define VSCALE 1024.0f
#define SPITCH 136   // smem staging row pitch in halves (272B, 16B-aligned)

typedef __nv_bfloat16 bf16;

// ---------------- scratch -----------------------------------------------
__device__ __half g_wf[MQKV * CIN];                   // qkv weights fp16
__device__ __half g_wohf[CIN * CV];                   // Wo hi fp16
__device__ __half g_wolf[CIN * CV];                   // Wo lo fp16
__device__ __half g_xtf[(size_t)NB * HW * CIN];       // x^T fp16 [l, c]
__device__ float g_qk[(size_t)NB * 64 * HW];          // q,k rows fp32 [m<64, l]
__device__ __half g_vraw[(size_t)NB * CV * HW];       // V rows fp16 [v, l]
__device__ __half g_qkT[(size_t)NB * HW * 64];        // fp16 [l][0:32]=qT,[32:64]=kT
__device__ float g_sp[(size_t)NB * SSEG * HW];
__device__ float g_s[(size_t)NB * HW];
__device__ __half g_pf[(size_t)NB * HW * HW];         // P=exp(E) fp16 [j,i]
__device__ __half g_vf[(size_t)NB * CV * HW];         // (V/s)*1024 fp16 [v,i]
__device__ __half g_otf[(size_t)NB * HW * CV];        // O^T fp16 [l, v] (x VSCALE)

// ---------------- helpers -------------------------------------------------
static __device__ __forceinline__ uint32_t smem_u32(const void* p) {
    uint32_t a;
    asm("{ .reg .u64 t; cvta.to.shared.u64 t, %1; cvt.u32.u64 %0, t; }" : "=r"(a) : "l"(p));
    return a;
}
#define SW64(x)  ((x) ^ (((x) >> 3) & 0x30))
#define SW128(x) ((x) ^ (((x) >> 3) & 0x70))
#define LDSM4(r0, r1, r2, r3, addr) \
    asm volatile("ldmatrix.sync.aligned.m8n8.x4.shared.b16 {%0,%1,%2,%3}, [%4];" \
                 : "=r"(r0), "=r"(r1), "=r"(r2), "=r"(r3) : "r"(addr))
#define LDSM2(r0, r1, addr) \
    asm volatile("ldmatrix.sync.aligned.m8n8.x2.shared.b16 {%0,%1}, [%2];" \
                 : "=r"(r0), "=r"(r1) : "r"(addr))
#define MMA16816H(c, a, b) \
    asm volatile("mma.sync.aligned.m16n8k16.row.col.f32.f16.f16.f32 " \
                 "{%0,%1,%2,%3}, {%4,%5,%6,%7}, {%8,%9}, {%0,%1,%2,%3};" \
                 : "+f"((c)[0]), "+f"((c)[1]), "+f"((c)[2]), "+f"((c)[3]) \
                 : "r"((a)[0]), "r"((a)[1]), "r"((a)[2]), "r"((a)[3]), \
                   "r"((b)[0]), "r"((b)[1]))
#define CPA16(saddr, gptr) \
    asm volatile("cp.async.cg.shared.global [%0], [%1], 16;" :: "r"(saddr), "l"(gptr))
#define CPA_COMMIT() asm volatile("cp.async.commit_group;")
#define CPA_WAIT(N)  asm volatile("cp.async.wait_group %0;" :: "n"(N))

// ---------------- weight prep ----------------------------------------------
__global__ void split_w(const float* __restrict__ Wq, const float* __restrict__ Wk,
                        const float* __restrict__ Wv, const float* __restrict__ Wo) {
    int i = blockIdx.x * 256 + threadIdx.x;
    if (i < MQKV * CIN) {
        float v = (i < CQK * CIN) ? Wq[i]
                : (i < 2 * CQK * CIN) ? Wk[i - CQK * CIN]
                : Wv[i - 2 * CQK * CIN];
        g_wf[i] = __float2half(v);
    } else {
        int j = i - MQKV * CIN;
        if (j < CIN * CV) {
            float v = Wo[j];
            __half h = __float2half(v);
            g_wohf[j] = h;
            g_wolf[j] = __float2half(v - __half2float(h));
        }
    }
}

// ---------------- transpose -> single fp16: src[R,HW] -> dst[HW,R] ----------
__global__ __launch_bounds__(256)
void trsp_h(const float* __restrict__ src, __half* __restrict__ dst,
            int R, size_t sStride, size_t dStride) {
    __shared__ float t[32][33];
    int n = blockIdx.z;
    src += (size_t)n * sStride;
    dst += (size_t)n * dStride;
    int c0 = blockIdx.x * 32, r0 = blockIdx.y * 32;
    int tx = threadIdx.x, ty = threadIdx.y;
    #pragma unroll
    for (int it = 0; it < 4; it++)
        t[ty + 8 * it][tx] = src[(size_t)(r0 + ty + 8 * it) * HW + c0 + tx];
    __syncthreads();
    #pragma unroll
    for (int it = 0; it < 4; it++)
        dst[(size_t)(c0 + ty + 8 * it) * R + r0 + tx] = __float2half(t[tx][ty + 8 * it]);
}

// ---------------- QKV projection: single fp16 product -----------------------
__global__ __launch_bounds__(256, 2)
void qkv_hmma() {
    __shared__ __align__(16) __half sA[64 * 32];
    __shared__ __align__(16) __half sB[128 * 32];
    int tid = threadIdx.x, lane = tid & 31, wid = tid >> 5;
    int wm = wid & 1, wn = wid >> 1;
    int n = blockIdx.z, m0 = blockIdx.y * 64, l0 = blockIdx.x * 128;

    const __half* xtf = g_xtf + (size_t)n * HW * CIN;
    uint32_t sa = smem_u32(sA), sb = smem_u32(sB);

    float acc[2][4][4] = {};

    for (int ck = 0; ck < CIN / 32; ck++) {
        {
            int row = tid >> 2, ch = tid & 3;
            uint32_t sw = SW64(row * 64 + ch * 16);
            *(float4*)((char*)sA + sw) =
                *(const float4*)(const void*)(g_wf + (size_t)(m0 + row) * CIN + ck * 32 + ch * 8);
        }
        #pragma unroll
        for (int t = 0; t < 2; t++) {
            int idx = tid + t * 256;
            int row = idx >> 2, ch = idx & 3;
            uint32_t sw = SW64(row * 64 + ch * 16);
            *(float4*)((char*)sB + sw) =
                *(const float4*)(const void*)(xtf + (size_t)(l0 + row) * CIN + ck * 32 + ch * 8);
        }
        __syncthreads();

        #pragma unroll
        for (int ks = 0; ks < 2; ks++) {
            uint32_t a[2][4], b[4][2];
            #pragma unroll
            for (int mt = 0; mt < 2; mt++) {
                int r = wm * 32 + mt * 16 + (lane & 15);
                uint32_t sw = SW64(r * 64 + ks * 32 + (lane >> 4) * 16);
                LDSM4(a[mt][0], a[mt][1], a[mt][2], a[mt][3], sa + sw);
            }
            #pragma unroll
            for (int nt = 0; nt < 4; nt++) {
                int r = wn * 32 + nt * 8 + (lane & 7);
                uint32_t sw = SW64(r * 64 + ks * 32 + ((lane >> 3) & 1) * 16);
                LDSM2(b[nt][0], b[nt][1], sb + sw);
            }
            #pragma unroll
            for (int mt = 0; mt < 2; mt++)
                #pragma unroll
                for (int nt = 0; nt < 4; nt++)
                    MMA16816H(acc[mt][nt], a[mt], b[nt]);
        }
        __syncthreads();
    }

    if (m0 == 0) {
        #pragma unroll
        for (int mt = 0; mt < 2; mt++) {
            int m = wm * 32 + mt * 16 + (lane >> 2);
            float* r0p = g_qk + ((size_t)n * 64 + m) * HW + l0 + wn * 32 + (lane & 3) * 2;
            float* r1p = r0p + 8 * HW;
            #pragma unroll
            for (int nt = 0; nt < 4; nt++) {
                *(float2*)(r0p + nt * 8) = make_float2(acc[mt][nt][0], acc[mt][nt][1]);
                *(float2*)(r1p + nt * 8) = make_float2(acc[mt][nt][2], acc[mt][nt][3]);
            }
        }
    } else {
        __half* vb = g_vraw + (size_t)n * CV * HW;
        #pragma unroll
        for (int mt = 0; mt < 2; mt++) {
            int v = m0 - 64 + wm * 32 + mt * 16 + (lane >> 2);
            __half* r0p = vb + (size_t)v * HW + l0 + wn * 32 + (lane & 3) * 2;
            __half* r1p = r0p + 8 * HW;
            #pragma unroll
            for (int nt = 0; nt < 4; nt++) {
                *(__half2*)(r0p + nt * 8) = __floats2half2_rn(acc[mt][nt][0], acc[mt][nt][1]);
                *(__half2*)(r1p + nt * 8) = __floats2half2_rn(acc[mt][nt][2], acc[mt][nt][3]);
            }
        }
    }
}

// ---------------- Et + exp fused, SMEM-staged coalesced P writes ------------
__global__ __launch_bounds__(256, 2)
void et_exp_hmma() {
    __shared__ __align__(16) char sm[128 * SPITCH * 2];  // 34816 B
    __half* sA = (__half*)sm;
    __half* sB = (__half*)(sm + 8192);
    __half* sP = (__half*)sm;

    int tid = threadIdx.x, lane = tid & 31, wid = tid >> 5;
    int wm = wid & 1, wn = wid >> 1;
    int n = blockIdx.z, i0 = blockIdx.x * 128, j0 = blockIdx.y * 128;

    const __half* t64 = g_qkT + (size_t)n * HW * 64;
    uint32_t sa = smem_u32(sA), sb = smem_u32(sB);

    #pragma unroll
    for (int t = 0; t < 2; t++) {
        int idx = tid + t * 256;
        int row = idx >> 2, ch = idx & 3;
        uint32_t sw = SW64(row * 64 + ch * 16);
        *(float4*)((char*)sA + sw) = *(const float4*)(const void*)(t64 + (size_t)(j0 + row) * 64 + 32 + ch * 8);
        *(float4*)((char*)sB + sw) = *(const float4*)(const void*)(t64 + (size_t)(i0 + row) * 64 + ch * 8);
    }
    __syncthreads();

    float acc[4][4][4] = {};
    #pragma unroll
    for (int ks = 0; ks < 2; ks++) {
        uint32_t a[4][4], b[4][2];
        #pragma unroll
        for (int mt = 0; mt < 4; mt++) {
            int r = wm * 64 + mt * 16 + (lane & 15);
            uint32_t sw = SW64(r * 64 + ks * 32 + (lane >> 4) * 16);
            LDSM4(a[mt][0], a[mt][1], a[mt][2], a[mt][3], sa + sw);
        }
        #pragma unroll
        for (int nt = 0; nt < 4; nt++) {
            int r = wn * 32 + nt * 8 + (lane & 7);
            uint32_t sw = SW64(r * 64 + ks * 32 + ((lane >> 3) & 1) * 16);
            LDSM2(b[nt][0], b[nt][1], sb + sw);
        }
        #pragma unroll
        for (int mt = 0; mt < 4; mt++)
            #pragma unroll
            for (int nt = 0; nt < 4; nt++)
                MMA16816H(acc[mt][nt], a[mt], b[nt]);
    }
    __syncthreads();   // A/B dead; reuse as P staging

    float cs[4][2];
    #pragma unroll
    for (int nt = 0; nt < 4; nt++) { cs[nt][0] = 0.0f; cs[nt][1] = 0.0f; }

    #pragma unroll
    for (int mt = 0; mt < 4; mt++) {
        int jl = wm * 64 + mt * 16 + (lane >> 2);
        #pragma unroll
        for (int nt = 0; nt < 4; nt++) {
            int il = wn * 32 + nt * 8 + (lane & 3) * 2;
            float p0 = __expf(acc[mt][nt][0]);
            float p1 = __expf(acc[mt][nt][1]);
            float p2 = __expf(acc[mt][nt][2]);
            float p3 = __expf(acc[mt][nt][3]);
            *(__half2*)(sP + jl * SPITCH + il) = __floats2half2_rn(p0, p1);
            *(__half2*)(sP + (jl + 8) * SPITCH + il) = __floats2half2_rn(p2, p3);
            cs[nt][0] += p0 + p2;
            cs[nt][1] += p1 + p3;
        }
    }
    int seg = blockIdx.y * 2 + wm;
    #pragma unroll
    for (int nt = 0; nt < 4; nt++) {
        #pragma unroll
        for (int c = 0; c < 2; c++) {
            float s = cs[nt][c];
            s += __shfl_xor_sync(0xFFFFFFFFu, s, 4);
            s += __shfl_xor_sync(0xFFFFFFFFu, s, 8);
            s += __shfl_xor_sync(0xFFFFFFFFu, s, 16);
            if ((lane >> 2) == 0) {
                int i = i0 + wn * 32 + nt * 8 + (lane & 3) * 2 + c;
                g_sp[((size_t)n * SSEG + seg) * HW + i] = s;
            }
        }
    }
    __syncthreads();

    __half* pf = g_pf + (size_t)n * HW * HW;
    #pragma unroll
    for (int it = 0; it < 8; it++) {
        int idx = tid + it * 256;
        int row = idx >> 4, sg = idx & 15;
        *(float4*)(pf + (size_t)(j0 + row) * HW + i0 + sg * 8) =
            *(const float4*)(sP + row * SPITCH + sg * 8);
    }
}

// ---------------- finalize col sums, V'' = V / s * VSCALE (fp16) ------------
__global__ __launch_bounds__(256)
void sum_fin() {
    size_t t = (size_t)blockIdx.x * 256 + threadIdx.x;
    size_t n = t / HW, i = t % HW;
    float s = 0.0f;
    #pragma unroll
    for (int sg = 0; sg < SSEG; sg++)
        s += g_sp[(n * SSEG + sg) * HW + i];
    g_s[t] = s;
}
__global__ __launch_bounds__(256)
void conv_v() {
    size_t idx = (size_t)blockIdx.x * 256 + threadIdx.x;
    size_t n = idx / ((size_t)CV * HW);
    size_t i = idx % HW;
    float v = __half2float(g_vraw[idx]);
    g_vf[idx] = __float2half(v / g_s[n * HW + i] * VSCALE);
}

// ---------------- O^T = P @ V''^T  fp16, cp.async pipelined -----------------
#define NCK (HW / 64)
__global__ __launch_bounds__(256, 2)
void mma_ot() {
    __shared__ __align__(16) __half sMem[4 * 128 * 64];   // 64 KB; staging needs 34816 B
    int tid = threadIdx.x, lane = tid & 31, wid = tid >> 5;
    int wm = wid & 1, wn = wid >> 1;
    int n = blockIdx.z, v0 = blockIdx.x * 128, j0 = blockIdx.y * 128;

    const __half* A = g_pf + (size_t)n * HW * HW + (size_t)j0 * HW;
    const __half* B = g_vf + ((size_t)n * CV + v0) * HW;
    uint32_t sa[2] = { smem_u32(sMem), smem_u32(sMem + 128 * 64) };
    uint32_t sb[2] = { smem_u32(sMem + 2 * 128 * 64), smem_u32(sMem + 3 * 128 * 64) };

    auto issue = [&](int ck, int buf) {
        #pragma unroll
        for (int t = 0; t < 4; t++) {
            int idx = tid + t * 256;
            int row = idx >> 3, c = idx & 7;
            uint32_t sw = SW128(row * 128 + c * 16);
            size_t go = (size_t)row * HW + (size_t)ck * 64 + c * 8;
            CPA16(sa[buf] + sw, A + go);
            CPA16(sb[buf] + sw, B + go);
        }
    };

    float acc[4][4][4] = {};

    issue(0, 0);
    CPA_COMMIT();
    for (int ck = 0; ck < NCK; ck++) {
        int buf = ck & 1;
        if (ck + 1 < NCK) {
            issue(ck + 1, buf ^ 1);
            CPA_COMMIT();
            CPA_WAIT(1);
        } else {
            CPA_WAIT(0);
        }
        __syncthreads();

        #pragma unroll
        for (int ks = 0; ks < 4; ks++) {
            uint32_t a[4][4], b[4][2];
            #pragma unroll
            for (int mt = 0; mt < 4; mt++) {
                int r = wm * 64 + mt * 16 + (lane & 15);
                uint32_t sw = SW128(r * 128 + ks * 32 + (lane >> 4) * 16);
                LDSM4(a[mt][0], a[mt][1], a[mt][2], a[mt][3], sa[buf] + sw);
            }
            #pragma unroll
            for (int nt = 0; nt < 4; nt++) {
                int r = wn * 32 + nt * 8 + (lane & 7);
                uint32_t sw = SW128(r * 128 + ks * 32 + ((lane >> 3) & 1) * 16);
                LDSM2(b[nt][0], b[nt][1], sb[buf] + sw);
            }
            #pragma unroll
            for (int mt = 0; mt < 4; mt++)
                #pragma unroll
                for (int nt = 0; nt < 4; nt++)
                    MMA16816H(acc[mt][nt], a[mt], b[nt]);
        }
        __syncthreads();
    }

    // single-pass staged, coalesced O^T fp16 write (128 rows x 256B = 16 segs)
    __half* stage = sMem;
    __half* otf = g_otf + (size_t)n * HW * CV;

    #pragma unroll
    for (int mt = 0; mt < 4; mt++) {
        int jl = wm * 64 + mt * 16 + (lane >> 2);
        int vc = wn * 32 + (lane & 3) * 2;
        #pragma unroll
        for (int nt = 0; nt < 4; nt++) {
            *(__half2*)(stage + jl * SPITCH + vc + nt * 8) =
                __floats2half2_rn(acc[mt][nt][0], acc[mt][nt][1]);
            *(__half2*)(stage + (jl + 8) * SPITCH + vc + nt * 8) =
                __floats2half2_rn(acc[mt][nt][2], acc[mt][nt][3]);
        }
    }
    __syncthreads();
    #pragma unroll
    for (int it = 0; it < 8; it++) {
        int idx = tid + it * 256;            // 128 rows x 16 segs(16B)
        int row = idx >> 4, sg = idx & 15;
        *(float4*)(otf + (size_t)(j0 + row) * CV + v0 + sg * 8) =
            *(const float4*)(stage + row * SPITCH + sg * 8);
    }
}

// ---------------- out = (gamma/VSCALE) * Wo @ O  (fp16 2-product) ------------
#define WCK (CV / 32)
__global__ __launch_bounds__(256, 2)
void wo_hmma(float* __restrict__ out, const float* __restrict__ gammaPtr) {
    __shared__ __align__(16) __half sAh[2][128 * 32], sAl[2][128 * 32];
    __shared__ __align__(16) __half sB[2][128 * 32];
    int tid = threadIdx.x, lane = tid & 31, wid = tid >> 5;
    int wm = wid & 1, wn = wid >> 1;
    int n = blockIdx.z, o0 = blockIdx.y * 128, l0 = blockIdx.x * 128;

    const __half* otf = g_otf + (size_t)n * HW * CV;
    uint32_t sa_h[2] = { smem_u32(sAh[0]), smem_u32(sAh[1]) };
    uint32_t sa_l[2] = { smem_u32(sAl[0]), smem_u32(sAl[1]) };
    uint32_t sb_[2]  = { smem_u32(sB[0]),  smem_u32(sB[1]) };

    auto issue = [&](int ck, int buf) {
        #pragma unroll
        for (int t = 0; t < 2; t++) {
            int idx = tid + t * 256;
            int row = idx >> 2, ch = idx & 3;
            uint32_t sw = SW64(row * 64 + ch * 16);
            size_t ga = (size_t)(o0 + row) * CV + ck * 32 + ch * 8;
            size_t gb = (size_t)(l0 + row) * CV + ck * 32 + ch * 8;
            CPA16(sa_h[buf] + sw, g_wohf + ga);
            CPA16(sa_l[buf] + sw, g_wolf + ga);
            CPA16(sb_[buf] + sw, otf + gb);
        }
    };

    float acc[4][4][4] = {};

    issue(0, 0);
    CPA_COMMIT();
    for (int ck = 0; ck < WCK; ck++) {
        int buf = ck & 1;
        if (ck + 1 < WCK) {
            issue(ck + 1, buf ^ 1);
            CPA_COMMIT();
            CPA_WAIT(1);
        } else {
            CPA_WAIT(0);
        }
        __syncthreads();

        #pragma unroll
        for (int ks = 0; ks < 2; ks++) {
            uint32_t a[4][4], b[4][2];
            uint32_t a_off[4];
            #pragma unroll
            for (int mt = 0; mt < 4; mt++) {
                int r = wm * 64 + mt * 16 + (lane & 15);
                a_off[mt] = SW64(r * 64 + ks * 32 + (lane >> 4) * 16);
                LDSM4(a[mt][0], a[mt][1], a[mt][2], a[mt][3], sa_h[buf] + a_off[mt]);
            }
            #pragma unroll
            for (int nt = 0; nt < 4; nt++) {
                int r = wn * 32 + nt * 8 + (lane & 7);
                uint32_t sw = SW64(r * 64 + ks * 32 + ((lane >> 3) & 1) * 16);
                LDSM2(b[nt][0], b[nt][1], sb_[buf] + sw);
            }
            #pragma unroll
            for (int mt = 0; mt < 4; mt++)
                #pragma unroll
                for (int nt = 0; nt < 4; nt++)
                    MMA16816H(acc[mt][nt], a[mt], b[nt]);
            #pragma unroll
            for (int mt = 0; mt < 4; mt++)
                LDSM4(a[mt][0], a[mt][1], a[mt][2], a[mt][3], sa_l[buf] + a_off[mt]);
            #pragma unroll
            for (int mt = 0; mt < 4; mt++)
                #pragma unroll
                for (int nt = 0; nt < 4; nt++)
                    MMA16816H(acc[mt][nt], a[mt], b[nt]);
        }
        __syncthreads();
    }

    float gamma = *gammaPtr * (1.0f / VSCALE);
    #pragma unroll
    for (int mt = 0; mt < 4; mt++) {
        int o = o0 + wm * 64 + mt * 16 + (lane >> 2);
        float* r0p = out + ((size_t)n * CIN + o) * HW + l0 + wn * 32 + (lane & 3) * 2;
        float* r1p = r0p + 8 * HW;
        #pragma unroll
        for (int nt = 0; nt < 4; nt++) {
            *(float2*)(r0p + nt * 8) = make_float2(gamma * acc[mt][nt][0], gamma * acc[mt][nt][1]);
            *(float2*)(r1p + nt * 8) = make_float2(gamma * acc[mt][nt][2], gamma * acc[mt][nt][3]);
        }
    }
}

// ---------------- launch ----------------------------------------------------
extern "C" void kernel_launch(void* const* d_in, const int* in_sizes, int n_in,
                              void* d_out, int out_size) {
    const float* x     = (const float*)d_in[0];
    const float* Wq    = (const float*)d_in[1];
    const float* Wk    = (const float*)d_in[2];
    const float* Wv    = (const float*)d_in[3];
    const float* Wo    = (const float*)d_in[4];
    const float* gamma = (const float*)d_in[5];
    float* out = (float*)d_out;

    float* qk = nullptr;   cudaGetSymbolAddress((void**)&qk,  g_qk);
    __half* xtf = nullptr; cudaGetSymbolAddress((void**)&xtf, g_xtf);
    __half* qkT = nullptr; cudaGetSymbolAddress((void**)&qkT, g_qkT);

    // 1. weights: qkv fp16; Wo fp16 hi/lo
    split_w<<<(MQKV * CIN + CIN * CV + 255) / 256, 256>>>(Wq, Wk, Wv, Wo);
    // 2. xT -> fp16
    trsp_h<<<dim3(HW / 32, CIN / 32, NB), dim3(32, 8)>>>(
        x, xtf, CIN, (size_t)CIN * HW, (size_t)HW * CIN);
    // 3. QKV projection (q/k fp32; V fp16 direct)
    qkv_hmma<<<dim3(HW / 128, MQKV / 64, NB), 256>>>();
    // 4. qT/kT -> fp16
    trsp_h<<<dim3(HW / 32, 2, NB), dim3(32, 8)>>>(
        qk, qkT, 64, (size_t)64 * HW, (size_t)HW * 64);
    // 5. Et + exp fused -> P fp16 (coalesced), partial col sums
    et_exp_hmma<<<dim3(HW / 128, HW / 128, NB), 256>>>();
    // 6. finalize sums; V'' fp16
    sum_fin<<<(NB * HW) / 256, 256>>>();
    conv_v<<<(NB * CV * HW) / 256, 256>>>();
    // 7. O^T = P @ V''^T (fp16, pipelined, single-pass fp16 epilogue)
    mma_ot<<<dim3(CV / 128, HW / 128, NB), 256>>>();
    // 8. out = (gamma/VSCALE) * Wo @ O (fp16 2-product, pipelined)
    wo_hmma<<<dim3(HW / 128, CIN / 128, NB), 256>>>(out, gamma);
}